// round 2
// baseline (speedup 1.0000x reference)
#include <cuda_runtime.h>
#include <math.h>

#define BB 8
#define MM 1024
#define EE 1536
#define DD 256
#define HH 8
#define DH 32
#define LN_EPS 1e-5f

// ---------------- scratch (static device globals; no allocation) ----------------
__device__ float g_qkv[BB*MM*3*DD];   // [b, m, 768]
__device__ float g_attn[BB*MM*DD];    // attention output pre out-proj
__device__ float g_A[BB*MM*DD];       // MHA output
__device__ float g_S[BB*EE*DD];       // scores  inc^T @ A
__device__ float g_edge[BB*EE*DD];    // S * softmax_e(S)
__device__ float g_Ep[BB*EE*DD];      // edge @ Wproj^T (pre-LN)
__device__ float g_E0[BB*EE*DD];      // LN(...)  -> base edge features
__device__ float g_Y1[BB*MM*DD];      // inc @ E0
__device__ float g_Y[BB*MM*DD];       // Y1 @ ec_Wproj^T
__device__ float g_mu[BB*MM];
__device__ float g_var[BB*MM];

// ---------------- generic 128x128x8 fp32 GEMM ----------------
// C[M,N] = opA(A) @ opB(B) (+ bias)
// TA=false: A is [M,K] row-major.  TA=true: A is [K,M] row-major (access A[k][m]).
// WB=true : B is weight layout [N,K] row-major (computes A @ B^T).
// WB=false: B is [K,N] row-major.
template<bool TA, bool WB, bool BIAS>
__global__ void __launch_bounds__(256)
gemm_tile(const float* __restrict__ A, const float* __restrict__ Bw,
          const float* __restrict__ bias, float* __restrict__ C,
          int Mdim, int Ndim, int Kdim,
          long strideA, long strideB, long strideC)
{
    A  += (long)blockIdx.z * strideA;
    Bw += (long)blockIdx.z * strideB;
    C  += (long)blockIdx.z * strideC;

    const int m0 = blockIdx.y * 128;
    const int n0 = blockIdx.x * 128;
    const int tid = threadIdx.x;
    const int rbase = (tid >> 4) * 8;
    const int cbase = (tid & 15) * 8;

    __shared__ float As[8][128];
    __shared__ float Bs[8][128];

    float acc[8][8];
#pragma unroll
    for (int i = 0; i < 8; i++)
#pragma unroll
        for (int j = 0; j < 8; j++) acc[i][j] = 0.f;

    for (int kt = 0; kt < Kdim; kt += 8) {
        if (!TA) {
            int ar = tid >> 1, ac = (tid & 1) * 4;
            float4 v = *(const float4*)(A + (size_t)(m0 + ar) * Kdim + kt + ac);
            As[ac + 0][ar] = v.x; As[ac + 1][ar] = v.y;
            As[ac + 2][ar] = v.z; As[ac + 3][ar] = v.w;
        } else {
            int ak = tid >> 5, am = (tid & 31) * 4;
            float4 v = *(const float4*)(A + (size_t)(kt + ak) * Mdim + m0 + am);
            *(float4*)&As[ak][am] = v;
        }
        if (WB) {
            int br = tid >> 1, bc = (tid & 1) * 4;
            float4 v = *(const float4*)(Bw + (size_t)(n0 + br) * Kdim + kt + bc);
            Bs[bc + 0][br] = v.x; Bs[bc + 1][br] = v.y;
            Bs[bc + 2][br] = v.z; Bs[bc + 3][br] = v.w;
        } else {
            int bk = tid >> 5, bn = (tid & 31) * 4;
            float4 v = *(const float4*)(Bw + (size_t)(kt + bk) * Ndim + n0 + bn);
            *(float4*)&Bs[bk][bn] = v;
        }
        __syncthreads();
#pragma unroll
        for (int k = 0; k < 8; k++) {
            float a[8], bf[8];
            *(float4*)(a)     = *(float4*)&As[k][rbase];
            *(float4*)(a + 4) = *(float4*)&As[k][rbase + 4];
            *(float4*)(bf)     = *(float4*)&Bs[k][cbase];
            *(float4*)(bf + 4) = *(float4*)&Bs[k][cbase + 4];
#pragma unroll
            for (int i = 0; i < 8; i++)
#pragma unroll
                for (int j = 0; j < 8; j++) acc[i][j] += a[i] * bf[j];
        }
        __syncthreads();
    }

#pragma unroll
    for (int i = 0; i < 8; i++) {
        float* crow = C + (size_t)(m0 + rbase + i) * Ndim + n0 + cbase;
        float out[8];
#pragma unroll
        for (int j = 0; j < 8; j++) {
            float v = acc[i][j];
            if (BIAS) v += bias[n0 + cbase + j];
            out[j] = v;
        }
        *(float4*)crow       = *(float4*)(out);
        *(float4*)(crow + 4) = *(float4*)(out + 4);
    }
}

// ---------------- fused attention (dh = 32 in registers) ----------------
// grid: (b*h, M/128), block 128.  scores tiny -> exp without max subtraction.
__global__ void __launch_bounds__(128)
attn_kernel(const float* __restrict__ qkv, float* __restrict__ out)
{
    const int bh = blockIdx.x;
    const int b = bh / HH, h = bh % HH;
    const int tid = threadIdx.x;
    const int qrow = blockIdx.y * 128 + tid;

    __shared__ float Kt[128][32];
    __shared__ float Vt[128][32];

    float q[32];
    const float* qp = qkv + ((size_t)(b * MM + qrow)) * 768 + h * 32;
    const float scale = 0.17677669529663687f; // 1/sqrt(32)
#pragma unroll
    for (int j = 0; j < 32; j++) q[j] = qp[j] * scale;

    float acc[32];
#pragma unroll
    for (int j = 0; j < 32; j++) acc[j] = 0.f;
    float l = 0.f;

    for (int kt = 0; kt < MM; kt += 128) {
#pragma unroll
        for (int i = 0; i < 8; i++) {
            int idx = tid + i * 128;
            int r = idx >> 3;
            int c = (idx & 7) * 4;
            const float* src = qkv + ((size_t)(b * MM + kt + r)) * 768 + 256 + h * 32 + c;
            *(float4*)&Kt[r][c] = *(const float4*)src;
            *(float4*)&Vt[r][c] = *(const float4*)(src + 256);
        }
        __syncthreads();
#pragma unroll 4
        for (int r = 0; r < 128; r++) {
            float s = 0.f;
#pragma unroll
            for (int j = 0; j < 32; j++) s += q[j] * Kt[r][j];
            float p = __expf(s);
            l += p;
#pragma unroll
            for (int j = 0; j < 32; j++) acc[j] += p * Vt[r][j];
        }
        __syncthreads();
    }

    float inv = 1.f / l;
    float* op = out + ((size_t)(b * MM + qrow)) * DD + h * 32;
#pragma unroll
    for (int j = 0; j < 32; j++) op[j] = acc[j] * inv;
}

// ---------------- softmax over edge dim (axis e of [b,e,d]) + multiply ----------------
// grid (DD/32, BB), block (32,32)
__global__ void softmax_edge_kernel(const float* __restrict__ S, float* __restrict__ O)
{
    const int b = blockIdx.y;
    const int tx = threadIdx.x, ty = threadIdx.y;
    const int d = blockIdx.x * 32 + tx;
    __shared__ float sm[32][32];

    const float* Sb = S + (size_t)b * EE * DD + d;
    float mx = -1e30f;
    for (int e = ty; e < EE; e += 32) mx = fmaxf(mx, Sb[(size_t)e * DD]);
    sm[ty][tx] = mx; __syncthreads();
    for (int s = 16; s > 0; s >>= 1) {
        if (ty < s) sm[ty][tx] = fmaxf(sm[ty][tx], sm[ty + s][tx]);
        __syncthreads();
    }
    mx = sm[0][tx]; __syncthreads();

    float sum = 0.f;
    for (int e = ty; e < EE; e += 32) sum += __expf(Sb[(size_t)e * DD] - mx);
    sm[ty][tx] = sum; __syncthreads();
    for (int s = 16; s > 0; s >>= 1) {
        if (ty < s) sm[ty][tx] += sm[ty + s][tx];
        __syncthreads();
    }
    sum = sm[0][tx];

    float inv = 1.f / sum;
    float* Ob = O + (size_t)b * EE * DD + d;
    for (int e = ty; e < EE; e += 32) {
        float v = Sb[(size_t)e * DD];
        Ob[(size_t)e * DD] = v * __expf(v - mx) * inv;
    }
}

// ---------------- block-wide reductions over D=256 ----------------
__device__ __forceinline__ float warp_sum(float v) {
#pragma unroll
    for (int o = 16; o > 0; o >>= 1) v += __shfl_down_sync(0xffffffffu, v, o);
    return v;
}

// LayerNorm: one block (256 threads) per row
__global__ void ln_kernel(const float* __restrict__ X, const float* __restrict__ g,
                          const float* __restrict__ bb, float* __restrict__ Y)
{
    const int row = blockIdx.x;
    const int d = threadIdx.x;
    const int lane = d & 31, w = d >> 5;
    __shared__ float red[8];
    __shared__ float bc;

    float x = X[(size_t)row * DD + d];

    float v = warp_sum(x);
    if (lane == 0) red[w] = v;
    __syncthreads();
    if (w == 0) {
        float t = (lane < 8) ? red[lane] : 0.f;
#pragma unroll
        for (int o = 4; o > 0; o >>= 1) t += __shfl_down_sync(0xffffffffu, t, o);
        if (lane == 0) bc = t;
    }
    __syncthreads();
    float mu = bc * (1.f / DD);
    float dv = x - mu;
    __syncthreads();

    v = warp_sum(dv * dv);
    if (lane == 0) red[w] = v;
    __syncthreads();
    if (w == 0) {
        float t = (lane < 8) ? red[lane] : 0.f;
#pragma unroll
        for (int o = 4; o > 0; o >>= 1) t += __shfl_down_sync(0xffffffffu, t, o);
        if (lane == 0) bc = t;
    }
    __syncthreads();
    float var = bc * (1.f / DD);

    Y[(size_t)row * DD + d] = dv * rsqrtf(var + LN_EPS) * g[d] + bb[d];
}

// Row stats only (for Y): mu, var per row
__global__ void stats_kernel(const float* __restrict__ X, float* __restrict__ mu_o,
                             float* __restrict__ var_o)
{
    const int row = blockIdx.x;
    const int d = threadIdx.x;
    const int lane = d & 31, w = d >> 5;
    __shared__ float red[8];
    __shared__ float bc;

    float x = X[(size_t)row * DD + d];

    float v = warp_sum(x);
    if (lane == 0) red[w] = v;
    __syncthreads();
    if (w == 0) {
        float t = (lane < 8) ? red[lane] : 0.f;
#pragma unroll
        for (int o = 4; o > 0; o >>= 1) t += __shfl_down_sync(0xffffffffu, t, o);
        if (lane == 0) bc = t;
    }
    __syncthreads();
    float mu = bc * (1.f / DD);
    float dv = x - mu;
    __syncthreads();

    v = warp_sum(dv * dv);
    if (lane == 0) red[w] = v;
    __syncthreads();
    if (w == 0) {
        float t = (lane < 8) ? red[lane] : 0.f;
#pragma unroll
        for (int o = 4; o > 0; o >>= 1) t += __shfl_down_sync(0xffffffffu, t, o);
        if (lane == 0) bc = t;
    }
    __syncthreads();
    if (d == 0) { mu_o[row] = mu; var_o[row] = bc * (1.f / DD); }
}

// ---------------- final node output ----------------
// n2 = (1+ae)^3 f + (1-ae) [ (1+ae)^2 LN(Y) + (1+ae) LN(2Y) + LN((3+av) Y) ]
// LN(cY) computed from Y's per-row (mu, var):  c*(Y-mu)*rsqrt(c^2 var + eps)*g + b
__global__ void final_node_kernel(const float* __restrict__ Y, const float* __restrict__ mu,
                                  const float* __restrict__ var, const float* __restrict__ feat,
                                  const float* __restrict__ g, const float* __restrict__ bb,
                                  const float* __restrict__ p_av, const float* __restrict__ p_ae,
                                  float* __restrict__ out)
{
    const int row = blockIdx.x;
    const int d = threadIdx.x;
    const float ae = *p_ae, av = *p_av;
    const float z  = Y[(size_t)row * DD + d] - mu[row];
    const float vr = var[row];
    const float gd = g[d], bd = bb[d];

    const float c3 = 3.f + av;
    const float t1 = z * rsqrtf(vr + LN_EPS) * gd + bd;
    const float t2 = 2.f * z * rsqrtf(4.f * vr + LN_EPS) * gd + bd;
    const float t3 = c3 * z * rsqrtf(c3 * c3 * vr + LN_EPS) * gd + bd;

    const float op = 1.f + ae;
    out[(size_t)row * DD + d] =
        op * op * op * feat[(size_t)row * DD + d] +
        (1.f - ae) * (op * op * t1 + op * t2 + t3);
}

// edge output: (3 + av) * E0
__global__ void edge_scale_kernel(const float* __restrict__ in, float* __restrict__ out,
                                  const float* __restrict__ p_av, int n4)
{
    int i = blockIdx.x * blockDim.x + threadIdx.x;
    if (i >= n4) return;
    float s = 3.f + *p_av;
    float4 v = ((const float4*)in)[i];
    v.x *= s; v.y *= s; v.z *= s; v.w *= s;
    ((float4*)out)[i] = v;
}

__global__ void copy4_kernel(const float* __restrict__ in, float* __restrict__ out, int n4)
{
    int i = blockIdx.x * blockDim.x + threadIdx.x;
    if (i < n4) ((float4*)out)[i] = ((const float4*)in)[i];
}

// ---------------- host ----------------
extern "C" void kernel_launch(void* const* d_in, const int* in_sizes, int n_in,
                              void* d_out, int out_size)
{
    const float* feat     = (const float*)d_in[0];
    const float* inc      = (const float*)d_in[1];
    const float* vc_Win   = (const float*)d_in[2];
    const float* vc_bin   = (const float*)d_in[3];
    const float* vc_Wout  = (const float*)d_in[4];
    const float* vc_bout  = (const float*)d_in[5];
    const float* vc_Wproj = (const float*)d_in[6];
    const float* vc_g     = (const float*)d_in[7];
    const float* vc_b     = (const float*)d_in[8];
    const float* vc_alpha = (const float*)d_in[9];
    const float* ec_Wproj = (const float*)d_in[14];
    const float* ec_g     = (const float*)d_in[15];
    const float* ec_b     = (const float*)d_in[16];
    const float* ec_alpha = (const float*)d_in[17];

    float *qkv, *attn, *A, *S, *edge, *Ep, *E0, *Y1, *Y, *mu, *var;
    cudaGetSymbolAddress((void**)&qkv,  g_qkv);
    cudaGetSymbolAddress((void**)&attn, g_attn);
    cudaGetSymbolAddress((void**)&A,    g_A);
    cudaGetSymbolAddress((void**)&S,    g_S);
    cudaGetSymbolAddress((void**)&edge, g_edge);
    cudaGetSymbolAddress((void**)&Ep,   g_Ep);
    cudaGetSymbolAddress((void**)&E0,   g_E0);
    cudaGetSymbolAddress((void**)&Y1,   g_Y1);
    cudaGetSymbolAddress((void**)&Y,    g_Y);
    cudaGetSymbolAddress((void**)&mu,   g_mu);
    cudaGetSymbolAddress((void**)&var,  g_var);

    const int NODE = BB * MM * DD;        // 2097152
    const int EDGE = BB * EE * DD;        // 3145728
    const int INC  = BB * MM * EE;        // 12582912
    float* out_node = (float*)d_out;
    float* out_edge = out_node + NODE;
    float* out_inc  = out_edge + EDGE;

    // 1) QKV = feat @ vc_Win^T + vc_bin       [8192 x 768], K=256
    gemm_tile<false, true, true><<<dim3(768 / 128, 8192 / 128, 1), 256>>>(
        feat, vc_Win, vc_bin, qkv, 8192, 768, 256, 0, 0, 0);

    // 2) attention
    attn_kernel<<<dim3(BB * HH, MM / 128), 128>>>(qkv, attn);

    // 3) A = attn @ vc_Wout^T + vc_bout       [8192 x 256], K=256
    gemm_tile<false, true, true><<<dim3(2, 64, 1), 256>>>(
        attn, vc_Wout, vc_bout, A, 8192, 256, 256, 0, 0, 0);

    // 4) S[b] = inc[b]^T @ A[b]               [1536 x 256], K=1024, batched over b
    gemm_tile<true, false, false><<<dim3(2, 12, BB), 256>>>(
        inc, A, nullptr, S, 1536, 256, 1024,
        (long)MM * EE, (long)MM * DD, (long)EE * DD);

    // 5) edge = S * softmax_e(S)
    softmax_edge_kernel<<<dim3(DD / 32, BB), dim3(32, 32)>>>(S, edge);

    // 6) Ep = edge @ vc_Wproj^T               [12288 x 256], K=256
    gemm_tile<false, true, false><<<dim3(2, 96, 1), 256>>>(
        edge, vc_Wproj, nullptr, Ep, 12288, 256, 256, 0, 0, 0);

    // 7) E0 = LN(Ep)
    ln_kernel<<<BB * EE, DD>>>(Ep, vc_g, vc_b, E0);

    // 8) Y1[b] = inc[b] @ E0[b]               [1024 x 256], K=1536, batched
    gemm_tile<false, false, false><<<dim3(2, 8, BB), 256>>>(
        inc, E0, nullptr, Y1, 1024, 256, 1536,
        (long)MM * EE, (long)EE * DD, (long)MM * DD);

    // 9) Y = Y1 @ ec_Wproj^T                  [8192 x 256], K=256
    gemm_tile<false, true, false><<<dim3(2, 64, 1), 256>>>(
        Y1, ec_Wproj, nullptr, Y, 8192, 256, 256, 0, 0, 0);

    // 10) row stats of Y
    stats_kernel<<<BB * MM, DD>>>(Y, mu, var);

    // 11) node output
    final_node_kernel<<<BB * MM, DD>>>(Y, mu, var, feat, ec_g, ec_b,
                                       vc_alpha, ec_alpha, out_node);

    // 12) edge output = (3 + av) * E0
    if (out_size >= NODE + EDGE) {
        int n4 = EDGE / 4;
        edge_scale_kernel<<<(n4 + 255) / 256, 256>>>(E0, out_edge, vc_alpha, n4);
    }

    // 13) inc passthrough
    if (out_size >= NODE + EDGE + INC) {
        int n4 = INC / 4;
        copy4_kernel<<<(n4 + 255) / 256, 256>>>(inc, out_inc, n4);
    }
}

// round 3
// speedup vs baseline: 1.4482x; 1.4482x over previous
#include <cuda_runtime.h>
#include <math.h>

#define BB 8
#define MM 1024
#define EE 1536
#define DD 256
#define HH 8
#define LN_EPS 1e-5f
#define CAP 256

// ---------------- scratch ----------------
__device__ float g_qkv[BB*MM*3*DD];
__device__ float g_attn[BB*MM*DD];
__device__ float g_A[BB*MM*DD];
__device__ float g_S[BB*EE*DD];
__device__ float g_edge[BB*EE*DD];
__device__ float g_Ep[BB*EE*DD];
__device__ float g_E0[BB*EE*DD];
__device__ float g_Y1[BB*MM*DD];
__device__ float g_Y[BB*MM*DD];
__device__ unsigned short g_csc_idx[(size_t)BB*EE*CAP];
__device__ int            g_csc_cnt[BB*EE];
__device__ unsigned short g_csr_idx[(size_t)BB*MM*CAP];
__device__ int            g_csr_cnt[BB*MM];

// ---------------- f32x2 helpers ----------------
__device__ __forceinline__ unsigned long long pack2(float x, float y) {
    unsigned long long r;
    asm("mov.b64 %0, {%1,%2};" : "=l"(r) : "r"(__float_as_int(x)), "r"(__float_as_int(y)));
    return r;
}
__device__ __forceinline__ void fma2(unsigned long long& d, unsigned long long a, unsigned long long b) {
    asm("fma.rn.f32x2 %0, %1, %2, %0;" : "+l"(d) : "l"(a), "l"(b));
}
__device__ __forceinline__ unsigned long long add2(unsigned long long a, unsigned long long b) {
    unsigned long long r;
    asm("add.rn.f32x2 %0, %1, %2;" : "=l"(r) : "l"(a), "l"(b));
    return r;
}
__device__ __forceinline__ float2 unpack2(unsigned long long v) {
    int x, y;
    asm("mov.b64 {%0,%1}, %2;" : "=r"(x), "=r"(y) : "l"(v));
    return make_float2(__int_as_float(x), __int_as_float(y));
}

// ---------------- dense GEMM: C = A[M,K] @ W[N,K]^T (+bias), f32x2 inner ----------------
template<bool BIAS>
__global__ void __launch_bounds__(256)
gemm_w(const float* __restrict__ A, const float* __restrict__ Bw,
       const float* __restrict__ bias, float* __restrict__ C,
       int Mdim, int Ndim, int Kdim)
{
    const int m0 = blockIdx.y * 128;
    const int n0 = blockIdx.x * 128;
    const int tid = threadIdx.x;
    const int rbase = (tid >> 4) * 8;
    const int cbase = (tid & 15) * 8;

    __shared__ float As[8][128];
    __shared__ float Bs[8][128];

    unsigned long long acc[8][4];
#pragma unroll
    for (int i = 0; i < 8; i++)
#pragma unroll
        for (int j = 0; j < 4; j++) acc[i][j] = 0ull;

    for (int kt = 0; kt < Kdim; kt += 8) {
        {
            int ar = tid >> 1, ac = (tid & 1) * 4;
            float4 v = *(const float4*)(A + (size_t)(m0 + ar) * Kdim + kt + ac);
            As[ac + 0][ar] = v.x; As[ac + 1][ar] = v.y;
            As[ac + 2][ar] = v.z; As[ac + 3][ar] = v.w;
            float4 w = *(const float4*)(Bw + (size_t)(n0 + ar) * Kdim + kt + ac);
            Bs[ac + 0][ar] = w.x; Bs[ac + 1][ar] = w.y;
            Bs[ac + 2][ar] = w.z; Bs[ac + 3][ar] = w.w;
        }
        __syncthreads();
#pragma unroll
        for (int k = 0; k < 8; k++) {
            float a[8];
            *(float4*)(a)     = *(float4*)&As[k][rbase];
            *(float4*)(a + 4) = *(float4*)&As[k][rbase + 4];
            const unsigned long long* bp = (const unsigned long long*)&Bs[k][cbase];
            unsigned long long b0 = bp[0], b1 = bp[1], b2 = bp[2], b3 = bp[3];
#pragma unroll
            for (int i = 0; i < 8; i++) {
                unsigned long long ad = pack2(a[i], a[i]);
                fma2(acc[i][0], ad, b0);
                fma2(acc[i][1], ad, b1);
                fma2(acc[i][2], ad, b2);
                fma2(acc[i][3], ad, b3);
            }
        }
        __syncthreads();
    }

#pragma unroll
    for (int i = 0; i < 8; i++) {
        float out[8];
#pragma unroll
        for (int j = 0; j < 4; j++) {
            float2 v = unpack2(acc[i][j]);
            out[2 * j] = v.x; out[2 * j + 1] = v.y;
        }
        if (BIAS) {
#pragma unroll
            for (int j = 0; j < 8; j++) out[j] += bias[n0 + cbase + j];
        }
        float* crow = C + (size_t)(m0 + rbase + i) * Ndim + n0 + cbase;
        *(float4*)crow       = *(float4*)(out);
        *(float4*)(crow + 4) = *(float4*)(out + 4);
    }
}

// ---------------- fused attention (dh=32), f32x2 ----------------
__global__ void __launch_bounds__(128)
attn_kernel(const float* __restrict__ qkv, float* __restrict__ out)
{
    const int bh = blockIdx.x;
    const int b = bh / HH, h = bh % HH;
    const int tid = threadIdx.x;
    const int qrow = blockIdx.y * 128 + tid;

    __shared__ float Kt[128][32];
    __shared__ float Vt[128][32];

    const float* qp = qkv + ((size_t)(b * MM + qrow)) * 768 + h * 32;
    const float scale = 0.17677669529663687f;
    unsigned long long q[16];
#pragma unroll
    for (int j = 0; j < 16; j++) q[j] = pack2(qp[2 * j] * scale, qp[2 * j + 1] * scale);

    unsigned long long acc[16];
#pragma unroll
    for (int j = 0; j < 16; j++) acc[j] = 0ull;
    float l = 0.f;

    for (int kt = 0; kt < MM; kt += 128) {
#pragma unroll
        for (int i = 0; i < 8; i++) {
            int idx = tid + i * 128;
            int r = idx >> 3;
            int c = (idx & 7) * 4;
            const float* src = qkv + ((size_t)(b * MM + kt + r)) * 768 + 256 + h * 32 + c;
            *(float4*)&Kt[r][c] = *(const float4*)src;
            *(float4*)&Vt[r][c] = *(const float4*)(src + 256);
        }
        __syncthreads();
#pragma unroll 2
        for (int r = 0; r < 128; r++) {
            const unsigned long long* kp = (const unsigned long long*)Kt[r];
            unsigned long long s0 = 0ull, s1 = 0ull, s2 = 0ull, s3 = 0ull;
#pragma unroll
            for (int j = 0; j < 16; j += 4) {
                fma2(s0, q[j],     kp[j]);
                fma2(s1, q[j + 1], kp[j + 1]);
                fma2(s2, q[j + 2], kp[j + 2]);
                fma2(s3, q[j + 3], kp[j + 3]);
            }
            float2 f = unpack2(add2(add2(s0, s1), add2(s2, s3)));
            float p = __expf(f.x + f.y);
            l += p;
            unsigned long long pd = pack2(p, p);
            const unsigned long long* vp = (const unsigned long long*)Vt[r];
#pragma unroll
            for (int j = 0; j < 16; j++) fma2(acc[j], pd, vp[j]);
        }
        __syncthreads();
    }

    float inv = 1.f / l;
    float* op = out + ((size_t)(b * MM + qrow)) * DD + h * 32;
#pragma unroll
    for (int j = 0; j < 16; j++) {
        float2 v = unpack2(acc[j]);
        op[2 * j] = v.x * inv; op[2 * j + 1] = v.y * inv;
    }
}

// ---------------- sparse index build ----------------
// CSC: per (b,e), list of m with inc[b,m,e] != 0. Thread per (b,e); coalesced over e.
__global__ void csc_build(const float* __restrict__ inc)
{
    int ge = blockIdx.x * blockDim.x + threadIdx.x;
    if (ge >= BB * EE) return;
    int b = ge / EE, e = ge % EE;
    const float* p = inc + (size_t)b * MM * EE + e;
    unsigned short* lst = g_csc_idx + (size_t)ge * CAP;
    int cnt = 0;
    for (int m = 0; m < MM; m++) {
        if (p[(size_t)m * EE] != 0.f) {
            if (cnt < CAP) lst[cnt] = (unsigned short)m;
            cnt++;
        }
    }
    g_csc_cnt[ge] = cnt < CAP ? cnt : CAP;
}

// CSR: per (b,m), list of e with inc[b,m,e] != 0. Warp per row, ballot compaction.
__global__ void csr_build(const float* __restrict__ inc)
{
    int wid = (blockIdx.x * blockDim.x + threadIdx.x) >> 5;
    int lane = threadIdx.x & 31;
    if (wid >= BB * MM) return;
    const float* p = inc + (size_t)wid * EE;
    unsigned short* lst = g_csr_idx + (size_t)wid * CAP;
    int cnt = 0;
    for (int eb = 0; eb < EE; eb += 32) {
        float v = p[eb + lane];
        unsigned mask = __ballot_sync(0xffffffffu, v != 0.f);
        if (v != 0.f) {
            int pos = cnt + __popc(mask & ((1u << lane) - 1u));
            if (pos < CAP) lst[pos] = (unsigned short)(eb + lane);
        }
        cnt += __popc(mask);
    }
    if (lane == 0) g_csr_cnt[wid] = cnt < CAP ? cnt : CAP;
}

// ---------------- sparse aggregation: O[g,:] = sum_{r in list(g)} X[base(g) + r,:] ----------------
// 64 threads per group (float4 over D=256), 4 groups per 256-thread block.
__global__ void __launch_bounds__(256)
spmm_gather(const unsigned short* __restrict__ idx, const int* __restrict__ cnt,
            const float* __restrict__ X, float* __restrict__ O, int groups_per_b, int rows_per_b)
{
    int g = blockIdx.x * 4 + (threadIdx.x >> 6);
    int b = g / groups_per_b;
    int t = threadIdx.x & 63;
    int c = cnt[g];
    const unsigned short* lst = idx + (size_t)g * CAP;
    const float* Xb = X + (size_t)b * rows_per_b * DD + t * 4;
    float4 s = make_float4(0.f, 0.f, 0.f, 0.f);
    int i = 0;
    for (; i + 4 <= c; i += 4) {
        int r0 = lst[i], r1 = lst[i + 1], r2 = lst[i + 2], r3 = lst[i + 3];
        float4 v0 = *(const float4*)(Xb + (size_t)r0 * DD);
        float4 v1 = *(const float4*)(Xb + (size_t)r1 * DD);
        float4 v2 = *(const float4*)(Xb + (size_t)r2 * DD);
        float4 v3 = *(const float4*)(Xb + (size_t)r3 * DD);
        s.x += v0.x; s.y += v0.y; s.z += v0.z; s.w += v0.w;
        s.x += v1.x; s.y += v1.y; s.z += v1.z; s.w += v1.w;
        s.x += v2.x; s.y += v2.y; s.z += v2.z; s.w += v2.w;
        s.x += v3.x; s.y += v3.y; s.z += v3.z; s.w += v3.w;
    }
    for (; i < c; i++) {
        int r = lst[i];
        float4 v = *(const float4*)(Xb + (size_t)r * DD);
        s.x += v.x; s.y += v.y; s.z += v.z; s.w += v.w;
    }
    *(float4*)(O + (size_t)g * DD + t * 4) = s;
}

// ---------------- softmax over edge dim + multiply ----------------
__global__ void softmax_edge_kernel(const float* __restrict__ S, float* __restrict__ O)
{
    const int b = blockIdx.y;
    const int tx = threadIdx.x, ty = threadIdx.y;
    const int d = blockIdx.x * 32 + tx;
    __shared__ float sm[32][32];

    const float* Sb = S + (size_t)b * EE * DD + d;
    float mx = -1e30f;
    for (int e = ty; e < EE; e += 32) mx = fmaxf(mx, Sb[(size_t)e * DD]);
    sm[ty][tx] = mx; __syncthreads();
    for (int s = 16; s > 0; s >>= 1) {
        if (ty < s) sm[ty][tx] = fmaxf(sm[ty][tx], sm[ty + s][tx]);
        __syncthreads();
    }
    mx = sm[0][tx]; __syncthreads();

    float sum = 0.f;
    for (int e = ty; e < EE; e += 32) sum += __expf(Sb[(size_t)e * DD] - mx);
    sm[ty][tx] = sum; __syncthreads();
    for (int s = 16; s > 0; s >>= 1) {
        if (ty < s) sm[ty][tx] += sm[ty + s][tx];
        __syncthreads();
    }
    sum = sm[0][tx];

    float inv = 1.f / sum;
    float* Ob = O + (size_t)b * EE * DD + d;
    for (int e = ty; e < EE; e += 32) {
        float v = Sb[(size_t)e * DD];
        Ob[(size_t)e * DD] = v * __expf(v - mx) * inv;
    }
}

// ---------------- reductions ----------------
__device__ __forceinline__ float warp_sum(float v) {
#pragma unroll
    for (int o = 16; o > 0; o >>= 1) v += __shfl_down_sync(0xffffffffu, v, o);
    return v;
}

__device__ __forceinline__ float block_sum256(float v, float* red, float* bc) {
    int lane = threadIdx.x & 31, w = threadIdx.x >> 5;
    float t = warp_sum(v);
    if (lane == 0) red[w] = t;
    __syncthreads();
    if (w == 0) {
        float u = (lane < 8) ? red[lane] : 0.f;
#pragma unroll
        for (int o = 4; o > 0; o >>= 1) u += __shfl_down_sync(0xffffffffu, u, o);
        if (lane == 0) *bc = u;
    }
    __syncthreads();
    return *bc;
}

// LN with dual output: E0 = LN(X), out_edge = (3+av) * E0
__global__ void ln_dual_kernel(const float* __restrict__ X, const float* __restrict__ g,
                               const float* __restrict__ bb, const float* __restrict__ p_av,
                               float* __restrict__ Y, float* __restrict__ out_edge)
{
    const int row = blockIdx.x;
    const int d = threadIdx.x;
    __shared__ float red[8];
    __shared__ float bc;

    float x = X[(size_t)row * DD + d];
    float mu = block_sum256(x, red, &bc) * (1.f / DD);
    float dv = x - mu;
    __syncthreads();
    float var = block_sum256(dv * dv, red, &bc) * (1.f / DD);

    float v = dv * rsqrtf(var + LN_EPS) * g[d] + bb[d];
    Y[(size_t)row * DD + d] = v;
    out_edge[(size_t)row * DD + d] = (3.f + *p_av) * v;
}

// fused stats + final node output
__global__ void final_node_kernel(const float* __restrict__ Y, const float* __restrict__ feat,
                                  const float* __restrict__ g, const float* __restrict__ bb,
                                  const float* __restrict__ p_av, const float* __restrict__ p_ae,
                                  float* __restrict__ out)
{
    const int row = blockIdx.x;
    const int d = threadIdx.x;
    __shared__ float red[8];
    __shared__ float bc;

    float y = Y[(size_t)row * DD + d];
    float mu = block_sum256(y, red, &bc) * (1.f / DD);
    float z = y - mu;
    __syncthreads();
    float vr = block_sum256(z * z, red, &bc) * (1.f / DD);

    const float ae = *p_ae, av = *p_av;
    const float gd = g[d], bd = bb[d];
    const float c3 = 3.f + av;
    const float t1 = z * rsqrtf(vr + LN_EPS) * gd + bd;
    const float t2 = 2.f * z * rsqrtf(4.f * vr + LN_EPS) * gd + bd;
    const float t3 = c3 * z * rsqrtf(c3 * c3 * vr + LN_EPS) * gd + bd;

    const float op = 1.f + ae;
    out[(size_t)row * DD + d] =
        op * op * op * feat[(size_t)row * DD + d] +
        (1.f - ae) * (op * op * t1 + op * t2 + t3);
}

__global__ void copy4_kernel(const float* __restrict__ in, float* __restrict__ out, int n4)
{
    int i = blockIdx.x * blockDim.x + threadIdx.x;
    if (i < n4) ((float4*)out)[i] = ((const float4*)in)[i];
}

// ---------------- host ----------------
extern "C" void kernel_launch(void* const* d_in, const int* in_sizes, int n_in,
                              void* d_out, int out_size)
{
    const float* feat     = (const float*)d_in[0];
    const float* inc      = (const float*)d_in[1];
    const float* vc_Win   = (const float*)d_in[2];
    const float* vc_bin   = (const float*)d_in[3];
    const float* vc_Wout  = (const float*)d_in[4];
    const float* vc_bout  = (const float*)d_in[5];
    const float* vc_Wproj = (const float*)d_in[6];
    const float* vc_g     = (const float*)d_in[7];
    const float* vc_b     = (const float*)d_in[8];
    const float* vc_alpha = (const float*)d_in[9];
    const float* ec_Wproj = (const float*)d_in[14];
    const float* ec_g     = (const float*)d_in[15];
    const float* ec_b     = (const float*)d_in[16];
    const float* ec_alpha = (const float*)d_in[17];

    float *qkv, *attn, *A, *S, *edge, *Ep, *E0, *Y1, *Y;
    unsigned short *csc_idx, *csr_idx;
    int *csc_cnt, *csr_cnt;
    cudaGetSymbolAddress((void**)&qkv,  g_qkv);
    cudaGetSymbolAddress((void**)&attn, g_attn);
    cudaGetSymbolAddress((void**)&A,    g_A);
    cudaGetSymbolAddress((void**)&S,    g_S);
    cudaGetSymbolAddress((void**)&edge, g_edge);
    cudaGetSymbolAddress((void**)&Ep,   g_Ep);
    cudaGetSymbolAddress((void**)&E0,   g_E0);
    cudaGetSymbolAddress((void**)&Y1,   g_Y1);
    cudaGetSymbolAddress((void**)&Y,    g_Y);
    cudaGetSymbolAddress((void**)&csc_idx, g_csc_idx);
    cudaGetSymbolAddress((void**)&csr_idx, g_csr_idx);
    cudaGetSymbolAddress((void**)&csc_cnt, g_csc_cnt);
    cudaGetSymbolAddress((void**)&csr_cnt, g_csr_cnt);

    const int NODE = BB * MM * DD;
    const int EDGE = BB * EE * DD;
    const int INC  = BB * MM * EE;
    float* out_node = (float*)d_out;
    float* out_edge = out_node + NODE;
    float* out_inc  = out_edge + EDGE;

    // index builds (only depend on inc)
    csc_build<<<(BB * EE + 255) / 256, 256>>>(inc);
    csr_build<<<(BB * MM * 32 + 255) / 256, 256>>>(inc);

    // 1) QKV = feat @ vc_Win^T + vc_bin       [8192 x 768]
    gemm_w<true><<<dim3(6, 64), 256>>>(feat, vc_Win, vc_bin, qkv, 8192, 768, 256);

    // 2) attention
    attn_kernel<<<dim3(BB * HH, MM / 128), 128>>>(qkv, attn);

    // 3) A = attn @ vc_Wout^T + vc_bout       [8192 x 256]
    gemm_w<true><<<dim3(2, 64), 256>>>(attn, vc_Wout, vc_bout, A, 8192, 256, 256);

    // 4) S[b,e,:] = sum_m inc[b,m,e] * A[b,m,:]  (sparse gather)
    spmm_gather<<<BB * EE / 4, 256>>>(csc_idx, csc_cnt, A, S, EE, MM);

    // 5) edge = S * softmax_e(S)
    softmax_edge_kernel<<<dim3(DD / 32, BB), dim3(32, 32)>>>(S, edge);

    // 6) Ep = edge @ vc_Wproj^T               [12288 x 256]
    gemm_w<false><<<dim3(2, 96), 256>>>(edge, vc_Wproj, nullptr, Ep, 12288, 256, 256);

    // 7) E0 = LN(Ep); out_edge = (3+av)*E0
    ln_dual_kernel<<<BB * EE, DD>>>(Ep, vc_g, vc_b, vc_alpha, E0, out_edge);

    // 8) Y1[b,m,:] = sum_e inc[b,m,e] * E0[b,e,:]  (sparse gather)
    spmm_gather<<<BB * MM / 4, 256>>>(csr_idx, csr_cnt, E0, Y1, MM, EE);

    // 9) Y = Y1 @ ec_Wproj^T                  [8192 x 256]
    gemm_w<false><<<dim3(2, 64), 256>>>(Y1, ec_Wproj, nullptr, Y, 8192, 256, 256);

    // 10) node output (fused stats + combine)
    final_node_kernel<<<BB * MM, DD>>>(Y, feat, ec_g, ec_b, vc_alpha, ec_alpha, out_node);

    // 11) inc passthrough
    if (out_size >= NODE + EDGE + INC) {
        int n4 = INC / 4;
        copy4_kernel<<<(n4 + 255) / 256, 256>>>(inc, out_inc, n4);
    }
}

// round 4
// speedup vs baseline: 2.8119x; 1.9416x over previous
#include <cuda_runtime.h>
#include <math.h>

#define BB 8
#define MM 1024
#define EE 1536
#define DD 256
#define HH 8
#define LN_EPS 1e-5f
#define CAP 256

// ---------------- scratch ----------------
__device__ float g_qkv[BB*MM*3*DD];
__device__ float g_attn[BB*MM*DD];
__device__ float g_A[BB*MM*DD];
__device__ float g_S[BB*EE*DD];
__device__ float g_edge[BB*EE*DD];
__device__ float g_Ep[BB*EE*DD];
__device__ float g_E0[BB*EE*DD];
__device__ float g_Y1[BB*MM*DD];
__device__ float g_Y[BB*MM*DD];
__device__ unsigned short g_csc_idx[(size_t)BB*EE*CAP];
__device__ int            g_csc_cnt[BB*EE];
__device__ unsigned short g_csr_idx[(size_t)BB*MM*CAP];
__device__ int            g_csr_cnt[BB*MM];

// ---------------- tf32 mma helpers ----------------
__device__ __forceinline__ unsigned tf32c(float f) {
    unsigned r;
    asm("cvt.rna.tf32.f32 %0, %1;" : "=r"(r) : "f"(f));
    return r;
}
__device__ __forceinline__ void mma_tf32(float4& d, unsigned a0, unsigned a1,
                                         unsigned a2, unsigned a3,
                                         unsigned b0, unsigned b1) {
    asm volatile(
        "mma.sync.aligned.m16n8k8.row.col.f32.tf32.tf32.f32 "
        "{%0,%1,%2,%3}, {%4,%5,%6,%7}, {%8,%9}, {%0,%1,%2,%3};"
        : "+f"(d.x), "+f"(d.y), "+f"(d.z), "+f"(d.w)
        : "r"(a0), "r"(a1), "r"(a2), "r"(a3), "r"(b0), "r"(b1));
}

// ---------------- dense GEMM via tf32 mma: C = A[M,K] @ W[N,K]^T (+bias) ----------------
// block 256 thr (8 warps 2x4), tile 128x128, BK=32, smem pad 36 (conflict-free frags)
template<bool BIAS>
__global__ void __launch_bounds__(256)
gemm_mma(const float* __restrict__ A, const float* __restrict__ W,
         const float* __restrict__ bias, float* __restrict__ C,
         int Mdim, int Ndim, int Kdim)
{
    const int m0 = blockIdx.y * 128;
    const int n0 = blockIdx.x * 128;
    const int tid = threadIdx.x;
    const int warp = tid >> 5, lane = tid & 31;
    const int wr = warp >> 2, wc = warp & 3;      // warp tile: 64x32
    const int g = lane >> 2, t = lane & 3;

    __shared__ unsigned As[128 * 36];
    __shared__ unsigned Bs[128 * 36];

    float4 acc[4][4];
#pragma unroll
    for (int i = 0; i < 4; i++)
#pragma unroll
        for (int j = 0; j < 4; j++) acc[i][j] = make_float4(0.f, 0.f, 0.f, 0.f);

    const int lr = tid >> 3;            // 0..31
    const int lc = (tid & 7) * 4;       // 0..28

    for (int kt = 0; kt < Kdim; kt += 32) {
#pragma unroll
        for (int p = 0; p < 4; p++) {
            int r = lr + p * 32;
            float4 va = *(const float4*)(A + (size_t)(m0 + r) * Kdim + kt + lc);
            float4 vb = *(const float4*)(W + (size_t)(n0 + r) * Kdim + kt + lc);
            uint4 ua = make_uint4(tf32c(va.x), tf32c(va.y), tf32c(va.z), tf32c(va.w));
            uint4 ub = make_uint4(tf32c(vb.x), tf32c(vb.y), tf32c(vb.z), tf32c(vb.w));
            *(uint4*)&As[r * 36 + lc] = ua;
            *(uint4*)&Bs[r * 36 + lc] = ub;
        }
        __syncthreads();
#pragma unroll
        for (int ks = 0; ks < 4; ks++) {
            const int k0 = ks * 8;
            unsigned af[4][4];
#pragma unroll
            for (int ms = 0; ms < 4; ms++) {
                int row = wr * 64 + ms * 16 + g;
                af[ms][0] = As[row * 36 + k0 + t];
                af[ms][1] = As[(row + 8) * 36 + k0 + t];
                af[ms][2] = As[row * 36 + k0 + 4 + t];
                af[ms][3] = As[(row + 8) * 36 + k0 + 4 + t];
            }
            unsigned bf[4][2];
#pragma unroll
            for (int ns = 0; ns < 4; ns++) {
                int nrow = wc * 32 + ns * 8 + g;
                bf[ns][0] = Bs[nrow * 36 + k0 + t];
                bf[ns][1] = Bs[nrow * 36 + k0 + 4 + t];
            }
#pragma unroll
            for (int ms = 0; ms < 4; ms++)
#pragma unroll
                for (int ns = 0; ns < 4; ns++)
                    mma_tf32(acc[ms][ns], af[ms][0], af[ms][1], af[ms][2], af[ms][3],
                             bf[ns][0], bf[ns][1]);
        }
        __syncthreads();
    }

#pragma unroll
    for (int ms = 0; ms < 4; ms++) {
        int r0 = m0 + wr * 64 + ms * 16 + g;
#pragma unroll
        for (int ns = 0; ns < 4; ns++) {
            int col = n0 + wc * 32 + ns * 8 + t * 2;
            float bx = 0.f, by = 0.f;
            if (BIAS) { bx = bias[col]; by = bias[col + 1]; }
            float2 v0 = make_float2(acc[ms][ns].x + bx, acc[ms][ns].y + by);
            float2 v1 = make_float2(acc[ms][ns].z + bx, acc[ms][ns].w + by);
            *(float2*)(C + (size_t)r0 * Ndim + col)       = v0;
            *(float2*)(C + (size_t)(r0 + 8) * Ndim + col) = v1;
        }
    }
}

// ---------------- attention via tf32 mma (dh=32) ----------------
// grid (64 bh, 8 qtiles), 256 thr (8 warps x 16 q rows). K/V chunks of 64 rows in smem.
__global__ void __launch_bounds__(256)
attn_mma(const float* __restrict__ qkv, float* __restrict__ out)
{
    const int bh = blockIdx.x;
    const int b = bh >> 3, h = bh & 7;
    const int tid = threadIdx.x;
    const int warp = tid >> 5, lane = tid & 31;
    const int g = lane >> 2, t = lane & 3;
    const int qw = blockIdx.y * 128 + warp * 16;

    __shared__ unsigned Ks[64 * 36];
    __shared__ unsigned Vs[64 * 36];

    // Q fragments (persistent), scaled
    const float scale = 0.17677669529663687f;
    unsigned qf[4][4];
    {
        const float* q0 = qkv + (size_t)(b * MM + qw + g) * 768 + h * 32;
        const float* q1 = qkv + (size_t)(b * MM + qw + g + 8) * 768 + h * 32;
#pragma unroll
        for (int ks = 0; ks < 4; ks++) {
            qf[ks][0] = tf32c(q0[ks * 8 + t] * scale);
            qf[ks][1] = tf32c(q1[ks * 8 + t] * scale);
            qf[ks][2] = tf32c(q0[ks * 8 + 4 + t] * scale);
            qf[ks][3] = tf32c(q1[ks * 8 + 4 + t] * scale);
        }
    }

    float4 o[4];
#pragma unroll
    for (int i = 0; i < 4; i++) o[i] = make_float4(0.f, 0.f, 0.f, 0.f);
    float l0 = 0.f, l1 = 0.f;

    const int lr = tid >> 3;        // 0..31
    const int lc = (tid & 7) * 4;   // 0..28
    const unsigned fullm = 0xffffffffu;
    const int src0 = (lane & 28) | (t >> 1);
    const int src2 = src0 + 2;
    const bool odd = (t & 1);

    for (int ch = 0; ch < 16; ch++) {
        const int kbase = ch * 64;
#pragma unroll
        for (int p = 0; p < 2; p++) {
            int r = lr + p * 32;
            const float* src = qkv + (size_t)(b * MM + kbase + r) * 768 + h * 32 + lc;
            float4 vk = *(const float4*)(src + 256);
            float4 vv = *(const float4*)(src + 512);
            *(uint4*)&Ks[r * 36 + lc] = make_uint4(tf32c(vk.x), tf32c(vk.y), tf32c(vk.z), tf32c(vk.w));
            *(uint4*)&Vs[r * 36 + lc] = make_uint4(tf32c(vv.x), tf32c(vv.y), tf32c(vv.z), tf32c(vv.w));
        }
        __syncthreads();

#pragma unroll
        for (int ns = 0; ns < 8; ns++) {
            // scores S (16 q x 8 kr)
            float4 s = make_float4(0.f, 0.f, 0.f, 0.f);
#pragma unroll
            for (int ks = 0; ks < 4; ks++) {
                int nrow = ns * 8 + g;
                unsigned b0 = Ks[nrow * 36 + ks * 8 + t];
                unsigned b1 = Ks[nrow * 36 + ks * 8 + 4 + t];
                mma_tf32(s, qf[ks][0], qf[ks][1], qf[ks][2], qf[ks][3], b0, b1);
            }
            // exp + row-sum accumulation
            s.x = __expf(s.x); s.y = __expf(s.y);
            s.z = __expf(s.z); s.w = __expf(s.w);
            l0 += s.x + s.y;
            l1 += s.z + s.w;
            // C-frag -> A-frag conversion (intra-quad shuffles)
            float x0 = __shfl_sync(fullm, s.x, src0);
            float y0 = __shfl_sync(fullm, s.y, src0);
            float z0 = __shfl_sync(fullm, s.z, src0);
            float w0 = __shfl_sync(fullm, s.w, src0);
            float x2 = __shfl_sync(fullm, s.x, src2);
            float y2 = __shfl_sync(fullm, s.y, src2);
            float z2 = __shfl_sync(fullm, s.z, src2);
            float w2 = __shfl_sync(fullm, s.w, src2);
            unsigned pa0 = tf32c(odd ? y0 : x0);
            unsigned pa1 = tf32c(odd ? w0 : z0);
            unsigned pa2 = tf32c(odd ? y2 : x2);
            unsigned pa3 = tf32c(odd ? w2 : z2);
            // PV: O += P(16xkr8) @ V(kr8 x d32)
#pragma unroll
            for (int ds = 0; ds < 4; ds++) {
                unsigned b0 = Vs[(ns * 8 + t) * 36 + ds * 8 + g];
                unsigned b1 = Vs[(ns * 8 + 4 + t) * 36 + ds * 8 + g];
                mma_tf32(o[ds], pa0, pa1, pa2, pa3, b0, b1);
            }
        }
        __syncthreads();
    }

    // row sums across quad
    l0 += __shfl_xor_sync(fullm, l0, 1);
    l0 += __shfl_xor_sync(fullm, l0, 2);
    l1 += __shfl_xor_sync(fullm, l1, 1);
    l1 += __shfl_xor_sync(fullm, l1, 2);
    float inv0 = 1.f / l0, inv1 = 1.f / l1;

    float* o0 = out + (size_t)(b * MM + qw + g) * DD + h * 32;
    float* o1 = out + (size_t)(b * MM + qw + g + 8) * DD + h * 32;
#pragma unroll
    for (int ds = 0; ds < 4; ds++) {
        int col = ds * 8 + t * 2;
        *(float2*)(o0 + col) = make_float2(o[ds].x * inv0, o[ds].y * inv0);
        *(float2*)(o1 + col) = make_float2(o[ds].z * inv1, o[ds].w * inv1);
    }
}

// ---------------- sparse index build ----------------
__global__ void csc_build(const float* __restrict__ inc)
{
    int ge = blockIdx.x * blockDim.x + threadIdx.x;
    if (ge >= BB * EE) return;
    int b = ge / EE, e = ge % EE;
    const float* p = inc + (size_t)b * MM * EE + e;
    unsigned short* lst = g_csc_idx + (size_t)ge * CAP;
    int cnt = 0;
    for (int m = 0; m < MM; m++) {
        if (p[(size_t)m * EE] != 0.f) {
            if (cnt < CAP) lst[cnt] = (unsigned short)m;
            cnt++;
        }
    }
    g_csc_cnt[ge] = cnt < CAP ? cnt : CAP;
}

__global__ void csr_build(const float* __restrict__ inc)
{
    int wid = (blockIdx.x * blockDim.x + threadIdx.x) >> 5;
    int lane = threadIdx.x & 31;
    if (wid >= BB * MM) return;
    const float* p = inc + (size_t)wid * EE;
    unsigned short* lst = g_csr_idx + (size_t)wid * CAP;
    int cnt = 0;
    for (int eb = 0; eb < EE; eb += 32) {
        float v = p[eb + lane];
        unsigned mask = __ballot_sync(0xffffffffu, v != 0.f);
        if (v != 0.f) {
            int pos = cnt + __popc(mask & ((1u << lane) - 1u));
            if (pos < CAP) lst[pos] = (unsigned short)(eb + lane);
        }
        cnt += __popc(mask);
    }
    if (lane == 0) g_csr_cnt[wid] = cnt < CAP ? cnt : CAP;
}

// ---------------- sparse aggregation ----------------
__global__ void __launch_bounds__(256)
spmm_gather(const unsigned short* __restrict__ idx, const int* __restrict__ cnt,
            const float* __restrict__ X, float* __restrict__ O, int groups_per_b, int rows_per_b)
{
    int g = blockIdx.x * 4 + (threadIdx.x >> 6);
    int b = g / groups_per_b;
    int t = threadIdx.x & 63;
    int c = cnt[g];
    const unsigned short* lst = idx + (size_t)g * CAP;
    const float* Xb = X + (size_t)b * rows_per_b * DD + t * 4;
    float4 s = make_float4(0.f, 0.f, 0.f, 0.f);
    int i = 0;
    for (; i + 4 <= c; i += 4) {
        int r0 = lst[i], r1 = lst[i + 1], r2 = lst[i + 2], r3 = lst[i + 3];
        float4 v0 = *(const float4*)(Xb + (size_t)r0 * DD);
        float4 v1 = *(const float4*)(Xb + (size_t)r1 * DD);
        float4 v2 = *(const float4*)(Xb + (size_t)r2 * DD);
        float4 v3 = *(const float4*)(Xb + (size_t)r3 * DD);
        s.x += v0.x; s.y += v0.y; s.z += v0.z; s.w += v0.w;
        s.x += v1.x; s.y += v1.y; s.z += v1.z; s.w += v1.w;
        s.x += v2.x; s.y += v2.y; s.z += v2.z; s.w += v2.w;
        s.x += v3.x; s.y += v3.y; s.z += v3.z; s.w += v3.w;
    }
    for (; i < c; i++) {
        int r = lst[i];
        float4 v = *(const float4*)(Xb + (size_t)r * DD);
        s.x += v.x; s.y += v.y; s.z += v.z; s.w += v.w;
    }
    *(float4*)(O + (size_t)g * DD + t * 4) = s;
}

// ---------------- softmax over edge dim + multiply ----------------
__global__ void softmax_edge_kernel(const float* __restrict__ S, float* __restrict__ O)
{
    const int b = blockIdx.y;
    const int tx = threadIdx.x, ty = threadIdx.y;
    const int d = blockIdx.x * 32 + tx;
    __shared__ float sm[32][32];

    const float* Sb = S + (size_t)b * EE * DD + d;
    float mx = -1e30f;
    for (int e = ty; e < EE; e += 32) mx = fmaxf(mx, Sb[(size_t)e * DD]);
    sm[ty][tx] = mx; __syncthreads();
    for (int s = 16; s > 0; s >>= 1) {
        if (ty < s) sm[ty][tx] = fmaxf(sm[ty][tx], sm[ty + s][tx]);
        __syncthreads();
    }
    mx = sm[0][tx]; __syncthreads();

    float sum = 0.f;
    for (int e = ty; e < EE; e += 32) sum += __expf(Sb[(size_t)e * DD] - mx);
    sm[ty][tx] = sum; __syncthreads();
    for (int s = 16; s > 0; s >>= 1) {
        if (ty < s) sm[ty][tx] += sm[ty + s][tx];
        __syncthreads();
    }
    sum = sm[0][tx];

    float inv = 1.f / sum;
    float* Ob = O + (size_t)b * EE * DD + d;
    for (int e = ty; e < EE; e += 32) {
        float v = Sb[(size_t)e * DD];
        Ob[(size_t)e * DD] = v * __expf(v - mx) * inv;
    }
}

// ---------------- reductions ----------------
__device__ __forceinline__ float warp_sum(float v) {
#pragma unroll
    for (int o = 16; o > 0; o >>= 1) v += __shfl_down_sync(0xffffffffu, v, o);
    return v;
}

__device__ __forceinline__ float block_sum256(float v, float* red, float* bc) {
    int lane = threadIdx.x & 31, w = threadIdx.x >> 5;
    float t = warp_sum(v);
    if (lane == 0) red[w] = t;
    __syncthreads();
    if (w == 0) {
        float u = (lane < 8) ? red[lane] : 0.f;
#pragma unroll
        for (int o = 4; o > 0; o >>= 1) u += __shfl_down_sync(0xffffffffu, u, o);
        if (lane == 0) *bc = u;
    }
    __syncthreads();
    return *bc;
}

__global__ void ln_dual_kernel(const float* __restrict__ X, const float* __restrict__ g,
                               const float* __restrict__ bb, const float* __restrict__ p_av,
                               float* __restrict__ Y, float* __restrict__ out_edge)
{
    const int row = blockIdx.x;
    const int d = threadIdx.x;
    __shared__ float red[8];
    __shared__ float bc;

    float x = X[(size_t)row * DD + d];
    float mu = block_sum256(x, red, &bc) * (1.f / DD);
    float dv = x - mu;
    __syncthreads();
    float var = block_sum256(dv * dv, red, &bc) * (1.f / DD);

    float v = dv * rsqrtf(var + LN_EPS) * g[d] + bb[d];
    Y[(size_t)row * DD + d] = v;
    out_edge[(size_t)row * DD + d] = (3.f + *p_av) * v;
}

__global__ void final_node_kernel(const float* __restrict__ Y, const float* __restrict__ feat,
                                  const float* __restrict__ g, const float* __restrict__ bb,
                                  const float* __restrict__ p_av, const float* __restrict__ p_ae,
                                  float* __restrict__ out)
{
    const int row = blockIdx.x;
    const int d = threadIdx.x;
    __shared__ float red[8];
    __shared__ float bc;

    float y = Y[(size_t)row * DD + d];
    float mu = block_sum256(y, red, &bc) * (1.f / DD);
    float z = y - mu;
    __syncthreads();
    float vr = block_sum256(z * z, red, &bc) * (1.f / DD);

    const float ae = *p_ae, av = *p_av;
    const float gd = g[d], bd = bb[d];
    const float c3 = 3.f + av;
    const float t1 = z * rsqrtf(vr + LN_EPS) * gd + bd;
    const float t2 = 2.f * z * rsqrtf(4.f * vr + LN_EPS) * gd + bd;
    const float t3 = c3 * z * rsqrtf(c3 * c3 * vr + LN_EPS) * gd + bd;

    const float op = 1.f + ae;
    out[(size_t)row * DD + d] =
        op * op * op * feat[(size_t)row * DD + d] +
        (1.f - ae) * (op * op * t1 + op * t2 + t3);
}

__global__ void copy4_kernel(const float* __restrict__ in, float* __restrict__ out, int n4)
{
    int i = blockIdx.x * blockDim.x + threadIdx.x;
    if (i < n4) ((float4*)out)[i] = ((const float4*)in)[i];
}

// ---------------- host ----------------
extern "C" void kernel_launch(void* const* d_in, const int* in_sizes, int n_in,
                              void* d_out, int out_size)
{
    const float* feat     = (const float*)d_in[0];
    const float* inc      = (const float*)d_in[1];
    const float* vc_Win   = (const float*)d_in[2];
    const float* vc_bin   = (const float*)d_in[3];
    const float* vc_Wout  = (const float*)d_in[4];
    const float* vc_bout  = (const float*)d_in[5];
    const float* vc_Wproj = (const float*)d_in[6];
    const float* vc_g     = (const float*)d_in[7];
    const float* vc_b     = (const float*)d_in[8];
    const float* vc_alpha = (const float*)d_in[9];
    const float* ec_Wproj = (const float*)d_in[14];
    const float* ec_g     = (const float*)d_in[15];
    const float* ec_b     = (const float*)d_in[16];
    const float* ec_alpha = (const float*)d_in[17];

    float *qkv, *attn, *A, *S, *edge, *Ep, *E0, *Y1, *Y;
    unsigned short *csc_idx, *csr_idx;
    int *csc_cnt, *csr_cnt;
    cudaGetSymbolAddress((void**)&qkv,  g_qkv);
    cudaGetSymbolAddress((void**)&attn, g_attn);
    cudaGetSymbolAddress((void**)&A,    g_A);
    cudaGetSymbolAddress((void**)&S,    g_S);
    cudaGetSymbolAddress((void**)&edge, g_edge);
    cudaGetSymbolAddress((void**)&Ep,   g_Ep);
    cudaGetSymbolAddress((void**)&E0,   g_E0);
    cudaGetSymbolAddress((void**)&Y1,   g_Y1);
    cudaGetSymbolAddress((void**)&Y,    g_Y);
    cudaGetSymbolAddress((void**)&csc_idx, g_csc_idx);
    cudaGetSymbolAddress((void**)&csr_idx, g_csr_idx);
    cudaGetSymbolAddress((void**)&csc_cnt, g_csc_cnt);
    cudaGetSymbolAddress((void**)&csr_cnt, g_csr_cnt);

    const int NODE = BB * MM * DD;
    const int EDGE = BB * EE * DD;
    const int INC  = BB * MM * EE;
    float* out_node = (float*)d_out;
    float* out_edge = out_node + NODE;
    float* out_inc  = out_edge + EDGE;

    // index builds
    csc_build<<<(BB * EE + 255) / 256, 256>>>(inc);
    csr_build<<<(BB * MM * 32 + 255) / 256, 256>>>(inc);

    // 1) QKV = feat @ vc_Win^T + vc_bin       [8192 x 768]
    gemm_mma<true><<<dim3(6, 64), 256>>>(feat, vc_Win, vc_bin, qkv, 8192, 768, 256);

    // 2) attention (tf32 mma)
    attn_mma<<<dim3(BB * HH, 8), 256>>>(qkv, attn);

    // 3) A = attn @ vc_Wout^T + vc_bout       [8192 x 256]
    gemm_mma<true><<<dim3(2, 64), 256>>>(attn, vc_Wout, vc_bout, A, 8192, 256, 256);

    // 4) S[b,e,:] = sum_m inc[b,m,e] * A[b,m,:]
    spmm_gather<<<BB * EE / 4, 256>>>(csc_idx, csc_cnt, A, S, EE, MM);

    // 5) edge = S * softmax_e(S)
    softmax_edge_kernel<<<dim3(DD / 32, BB), dim3(32, 32)>>>(S, edge);

    // 6) Ep = edge @ vc_Wproj^T               [12288 x 256]
    gemm_mma<false><<<dim3(2, 96), 256>>>(edge, vc_Wproj, nullptr, Ep, 12288, 256, 256);

    // 7) E0 = LN(Ep); out_edge = (3+av)*E0
    ln_dual_kernel<<<BB * EE, DD>>>(Ep, vc_g, vc_b, vc_alpha, E0, out_edge);

    // 8) Y1[b,m,:] = sum_e inc[b,m,e] * E0[b,e,:]
    spmm_gather<<<BB * MM / 4, 256>>>(csr_idx, csr_cnt, E0, Y1, MM, EE);

    // 9) Y = Y1 @ ec_Wproj^T                  [8192 x 256]
    gemm_mma<false><<<dim3(2, 64), 256>>>(Y1, ec_Wproj, nullptr, Y, 8192, 256, 256);

    // 10) node output
    final_node_kernel<<<BB * MM, DD>>>(Y, feat, ec_g, ec_b, vc_alpha, ec_alpha, out_node);

    // 11) inc passthrough
    if (out_size >= NODE + EDGE + INC) {
        int n4 = INC / 4;
        copy4_kernel<<<(n4 + 255) / 256, 256>>>(inc, out_inc, n4);
    }
}

// round 5
// speedup vs baseline: 2.8283x; 1.0058x over previous
#include <cuda_runtime.h>
#include <math.h>

#define BB 8
#define MM 1024
#define EE 1536
#define DD 256
#define HH 8
#define LN_EPS 1e-5f
#define CAP 256

// ---------------- scratch ----------------
__device__ float g_qkv[BB*MM*3*DD];
__device__ float g_attn[BB*MM*DD];
__device__ float g_A[BB*MM*DD];
__device__ float g_S[BB*EE*DD];
__device__ float g_edge[BB*EE*DD];
__device__ float g_Ep[BB*EE*DD];
__device__ float g_E0[BB*EE*DD];
__device__ float g_Y1[BB*MM*DD];
__device__ float g_Y[BB*MM*DD];
__device__ unsigned short g_csc_idx[(size_t)BB*EE*CAP];
__device__ int            g_csc_cnt[BB*EE];
__device__ unsigned short g_csr_idx[(size_t)BB*MM*CAP];
__device__ int            g_csr_cnt[BB*MM];

// ---------------- tf32 mma helpers ----------------
__device__ __forceinline__ unsigned tf32c(float f) {
    unsigned r;
    asm("cvt.rna.tf32.f32 %0, %1;" : "=r"(r) : "f"(f));
    return r;
}
__device__ __forceinline__ void mma_tf32(float4& d, unsigned a0, unsigned a1,
                                         unsigned a2, unsigned a3,
                                         unsigned b0, unsigned b1) {
    asm volatile(
        "mma.sync.aligned.m16n8k8.row.col.f32.tf32.tf32.f32 "
        "{%0,%1,%2,%3}, {%4,%5,%6,%7}, {%8,%9}, {%0,%1,%2,%3};"
        : "+f"(d.x), "+f"(d.y), "+f"(d.z), "+f"(d.w)
        : "r"(a0), "r"(a1), "r"(a2), "r"(a3), "r"(b0), "r"(b1));
}

// ---------------- dense GEMM via tf32 mma: C = A[M,K] @ W[N,K]^T (+bias) ----------------
template<bool BIAS>
__global__ void __launch_bounds__(256)
gemm_mma(const float* __restrict__ A, const float* __restrict__ W,
         const float* __restrict__ bias, float* __restrict__ C,
         int Mdim, int Ndim, int Kdim)
{
    const int m0 = blockIdx.y * 128;
    const int n0 = blockIdx.x * 128;
    const int tid = threadIdx.x;
    const int warp = tid >> 5, lane = tid & 31;
    const int wr = warp >> 2, wc = warp & 3;
    const int g = lane >> 2, t = lane & 3;

    __shared__ unsigned As[128 * 36];
    __shared__ unsigned Bs[128 * 36];

    float4 acc[4][4];
#pragma unroll
    for (int i = 0; i < 4; i++)
#pragma unroll
        for (int j = 0; j < 4; j++) acc[i][j] = make_float4(0.f, 0.f, 0.f, 0.f);

    const int lr = tid >> 3;
    const int lc = (tid & 7) * 4;

    for (int kt = 0; kt < Kdim; kt += 32) {
#pragma unroll
        for (int p = 0; p < 4; p++) {
            int r = lr + p * 32;
            float4 va = *(const float4*)(A + (size_t)(m0 + r) * Kdim + kt + lc);
            float4 vb = *(const float4*)(W + (size_t)(n0 + r) * Kdim + kt + lc);
            uint4 ua = make_uint4(tf32c(va.x), tf32c(va.y), tf32c(va.z), tf32c(va.w));
            uint4 ub = make_uint4(tf32c(vb.x), tf32c(vb.y), tf32c(vb.z), tf32c(vb.w));
            *(uint4*)&As[r * 36 + lc] = ua;
            *(uint4*)&Bs[r * 36 + lc] = ub;
        }
        __syncthreads();
#pragma unroll
        for (int ks = 0; ks < 4; ks++) {
            const int k0 = ks * 8;
            unsigned af[4][4];
#pragma unroll
            for (int ms = 0; ms < 4; ms++) {
                int row = wr * 64 + ms * 16 + g;
                af[ms][0] = As[row * 36 + k0 + t];
                af[ms][1] = As[(row + 8) * 36 + k0 + t];
                af[ms][2] = As[row * 36 + k0 + 4 + t];
                af[ms][3] = As[(row + 8) * 36 + k0 + 4 + t];
            }
            unsigned bf[4][2];
#pragma unroll
            for (int ns = 0; ns < 4; ns++) {
                int nrow = wc * 32 + ns * 8 + g;
                bf[ns][0] = Bs[nrow * 36 + k0 + t];
                bf[ns][1] = Bs[nrow * 36 + k0 + 4 + t];
            }
#pragma unroll
            for (int ms = 0; ms < 4; ms++)
#pragma unroll
                for (int ns = 0; ns < 4; ns++)
                    mma_tf32(acc[ms][ns], af[ms][0], af[ms][1], af[ms][2], af[ms][3],
                             bf[ns][0], bf[ns][1]);
        }
        __syncthreads();
    }

#pragma unroll
    for (int ms = 0; ms < 4; ms++) {
        int r0 = m0 + wr * 64 + ms * 16 + g;
#pragma unroll
        for (int ns = 0; ns < 4; ns++) {
            int col = n0 + wc * 32 + ns * 8 + t * 2;
            float bx = 0.f, by = 0.f;
            if (BIAS) { bx = bias[col]; by = bias[col + 1]; }
            float2 v0 = make_float2(acc[ms][ns].x + bx, acc[ms][ns].y + by);
            float2 v1 = make_float2(acc[ms][ns].z + bx, acc[ms][ns].w + by);
            *(float2*)(C + (size_t)r0 * Ndim + col)       = v0;
            *(float2*)(C + (size_t)(r0 + 8) * Ndim + col) = v1;
        }
    }
}

// ---------------- attention via tf32 mma (dh=32), 2x q-blocking ----------------
// grid (64 bh, 4 qtiles of 256), 256 thr (8 warps x 32 q rows).
// K stride 36 (bank 4g+t), V stride 40 (bank 8t+g) -> both conflict-free.
__global__ void __launch_bounds__(256, 2)
attn_mma(const float* __restrict__ qkv, float* __restrict__ out)
{
    const int bh = blockIdx.x;
    const int b = bh >> 3, h = bh & 7;
    const int tid = threadIdx.x;
    const int warp = tid >> 5, lane = tid & 31;
    const int g = lane >> 2, t = lane & 3;
    const int qw = blockIdx.y * 256 + warp * 32;

    __shared__ unsigned Ks[64 * 36];
    __shared__ unsigned Vs[64 * 40];

    const float scale = 0.17677669529663687f;
    unsigned qf[2][4][4];
#pragma unroll
    for (int qt = 0; qt < 2; qt++) {
        const float* q0 = qkv + (size_t)(b * MM + qw + qt * 16 + g) * 768 + h * 32;
        const float* q1 = qkv + (size_t)(b * MM + qw + qt * 16 + g + 8) * 768 + h * 32;
#pragma unroll
        for (int ks = 0; ks < 4; ks++) {
            qf[qt][ks][0] = tf32c(q0[ks * 8 + t] * scale);
            qf[qt][ks][1] = tf32c(q1[ks * 8 + t] * scale);
            qf[qt][ks][2] = tf32c(q0[ks * 8 + 4 + t] * scale);
            qf[qt][ks][3] = tf32c(q1[ks * 8 + 4 + t] * scale);
        }
    }

    float4 o0[4], o1[4];
#pragma unroll
    for (int i = 0; i < 4; i++) {
        o0[i] = make_float4(0.f, 0.f, 0.f, 0.f);
        o1[i] = make_float4(0.f, 0.f, 0.f, 0.f);
    }
    float l00 = 0.f, l01 = 0.f, l10 = 0.f, l11 = 0.f;

    const int lr = tid >> 3;
    const int lc = (tid & 7) * 4;
    const unsigned fullm = 0xffffffffu;
    const int src0 = (lane & 28) | (t >> 1);
    const int src2 = src0 + 2;
    const bool odd = (t & 1);

    for (int ch = 0; ch < 16; ch++) {
        const int kbase = ch * 64;
#pragma unroll
        for (int p = 0; p < 2; p++) {
            int r = lr + p * 32;
            const float* src = qkv + (size_t)(b * MM + kbase + r) * 768 + h * 32 + lc;
            float4 vk = *(const float4*)(src + 256);
            float4 vv = *(const float4*)(src + 512);
            *(uint4*)&Ks[r * 36 + lc] = make_uint4(tf32c(vk.x), tf32c(vk.y), tf32c(vk.z), tf32c(vk.w));
            *(uint4*)&Vs[r * 40 + lc] = make_uint4(tf32c(vv.x), tf32c(vv.y), tf32c(vv.z), tf32c(vv.w));
        }
        __syncthreads();

#pragma unroll
        for (int ns = 0; ns < 8; ns++) {
            float4 s0 = make_float4(0.f, 0.f, 0.f, 0.f);
            float4 s1 = make_float4(0.f, 0.f, 0.f, 0.f);
#pragma unroll
            for (int ks = 0; ks < 4; ks++) {
                int nrow = ns * 8 + g;
                unsigned b0 = Ks[nrow * 36 + ks * 8 + t];
                unsigned b1 = Ks[nrow * 36 + ks * 8 + 4 + t];
                mma_tf32(s0, qf[0][ks][0], qf[0][ks][1], qf[0][ks][2], qf[0][ks][3], b0, b1);
                mma_tf32(s1, qf[1][ks][0], qf[1][ks][1], qf[1][ks][2], qf[1][ks][3], b0, b1);
            }
            s0.x = __expf(s0.x); s0.y = __expf(s0.y); s0.z = __expf(s0.z); s0.w = __expf(s0.w);
            s1.x = __expf(s1.x); s1.y = __expf(s1.y); s1.z = __expf(s1.z); s1.w = __expf(s1.w);
            l00 += s0.x + s0.y; l01 += s0.z + s0.w;
            l10 += s1.x + s1.y; l11 += s1.z + s1.w;

            float ax0 = __shfl_sync(fullm, s0.x, src0);
            float ay0 = __shfl_sync(fullm, s0.y, src0);
            float az0 = __shfl_sync(fullm, s0.z, src0);
            float aw0 = __shfl_sync(fullm, s0.w, src0);
            float ax2 = __shfl_sync(fullm, s0.x, src2);
            float ay2 = __shfl_sync(fullm, s0.y, src2);
            float az2 = __shfl_sync(fullm, s0.z, src2);
            float aw2 = __shfl_sync(fullm, s0.w, src2);
            unsigned pa0 = tf32c(odd ? ay0 : ax0);
            unsigned pa1 = tf32c(odd ? aw0 : az0);
            unsigned pa2 = tf32c(odd ? ay2 : ax2);
            unsigned pa3 = tf32c(odd ? aw2 : az2);

            float bx0 = __shfl_sync(fullm, s1.x, src0);
            float by0 = __shfl_sync(fullm, s1.y, src0);
            float bz0 = __shfl_sync(fullm, s1.z, src0);
            float bw0 = __shfl_sync(fullm, s1.w, src0);
            float bx2 = __shfl_sync(fullm, s1.x, src2);
            float by2 = __shfl_sync(fullm, s1.y, src2);
            float bz2 = __shfl_sync(fullm, s1.z, src2);
            float bw2 = __shfl_sync(fullm, s1.w, src2);
            unsigned pb0 = tf32c(odd ? by0 : bx0);
            unsigned pb1 = tf32c(odd ? bw0 : bz0);
            unsigned pb2 = tf32c(odd ? by2 : bx2);
            unsigned pb3 = tf32c(odd ? bw2 : bz2);

#pragma unroll
            for (int ds = 0; ds < 4; ds++) {
                unsigned v0 = Vs[(ns * 8 + t) * 40 + ds * 8 + g];
                unsigned v1 = Vs[(ns * 8 + 4 + t) * 40 + ds * 8 + g];
                mma_tf32(o0[ds], pa0, pa1, pa2, pa3, v0, v1);
                mma_tf32(o1[ds], pb0, pb1, pb2, pb3, v0, v1);
            }
        }
        __syncthreads();
    }

    l00 += __shfl_xor_sync(fullm, l00, 1); l00 += __shfl_xor_sync(fullm, l00, 2);
    l01 += __shfl_xor_sync(fullm, l01, 1); l01 += __shfl_xor_sync(fullm, l01, 2);
    l10 += __shfl_xor_sync(fullm, l10, 1); l10 += __shfl_xor_sync(fullm, l10, 2);
    l11 += __shfl_xor_sync(fullm, l11, 1); l11 += __shfl_xor_sync(fullm, l11, 2);
    float i00 = 1.f / l00, i01 = 1.f / l01;
    float i10 = 1.f / l10, i11 = 1.f / l11;

    {
        float* p0 = out + (size_t)(b * MM + qw + g) * DD + h * 32;
        float* p1 = out + (size_t)(b * MM + qw + g + 8) * DD + h * 32;
#pragma unroll
        for (int ds = 0; ds < 4; ds++) {
            int col = ds * 8 + t * 2;
            *(float2*)(p0 + col) = make_float2(o0[ds].x * i00, o0[ds].y * i00);
            *(float2*)(p1 + col) = make_float2(o0[ds].z * i01, o0[ds].w * i01);
        }
        float* p2 = out + (size_t)(b * MM + qw + 16 + g) * DD + h * 32;
        float* p3 = out + (size_t)(b * MM + qw + 16 + g + 8) * DD + h * 32;
#pragma unroll
        for (int ds = 0; ds < 4; ds++) {
            int col = ds * 8 + t * 2;
            *(float2*)(p2 + col) = make_float2(o1[ds].x * i10, o1[ds].y * i10);
            *(float2*)(p3 + col) = make_float2(o1[ds].z * i11, o1[ds].w * i11);
        }
    }
}

// ---------------- sparse index build ----------------
__global__ void csc_build(const float* __restrict__ inc)
{
    int ge = blockIdx.x * blockDim.x + threadIdx.x;
    if (ge >= BB * EE) return;
    int b = ge / EE, e = ge % EE;
    const float* p = inc + (size_t)b * MM * EE + e;
    unsigned short* lst = g_csc_idx + (size_t)ge * CAP;
    int cnt = 0;
    for (int m = 0; m < MM; m++) {
        if (p[(size_t)m * EE] != 0.f) {
            if (cnt < CAP) lst[cnt] = (unsigned short)m;
            cnt++;
        }
    }
    g_csc_cnt[ge] = cnt < CAP ? cnt : CAP;
}

__global__ void csr_build(const float* __restrict__ inc)
{
    int wid = (blockIdx.x * blockDim.x + threadIdx.x) >> 5;
    int lane = threadIdx.x & 31;
    if (wid >= BB * MM) return;
    const float* p = inc + (size_t)wid * EE;
    unsigned short* lst = g_csr_idx + (size_t)wid * CAP;
    int cnt = 0;
    for (int eb = 0; eb < EE; eb += 32) {
        float v = p[eb + lane];
        unsigned mask = __ballot_sync(0xffffffffu, v != 0.f);
        if (v != 0.f) {
            int pos = cnt + __popc(mask & ((1u << lane) - 1u));
            if (pos < CAP) lst[pos] = (unsigned short)(eb + lane);
        }
        cnt += __popc(mask);
    }
    if (lane == 0) g_csr_cnt[wid] = cnt < CAP ? cnt : CAP;
}

// ---------------- sparse aggregation (unroll 8 for MLP) ----------------
__global__ void __launch_bounds__(256)
spmm_gather(const unsigned short* __restrict__ idx, const int* __restrict__ cnt,
            const float* __restrict__ X, float* __restrict__ O, int groups_per_b, int rows_per_b)
{
    int g = blockIdx.x * 4 + (threadIdx.x >> 6);
    int b = g / groups_per_b;
    int t = threadIdx.x & 63;
    int c = cnt[g];
    const unsigned short* lst = idx + (size_t)g * CAP;
    const float* Xb = X + (size_t)b * rows_per_b * DD + t * 4;
    float4 s = make_float4(0.f, 0.f, 0.f, 0.f);
    float4 s2 = make_float4(0.f, 0.f, 0.f, 0.f);
    int i = 0;
    for (; i + 8 <= c; i += 8) {
        int r0 = lst[i], r1 = lst[i+1], r2 = lst[i+2], r3 = lst[i+3];
        int r4 = lst[i+4], r5 = lst[i+5], r6 = lst[i+6], r7 = lst[i+7];
        float4 v0 = *(const float4*)(Xb + (size_t)r0 * DD);
        float4 v1 = *(const float4*)(Xb + (size_t)r1 * DD);
        float4 v2 = *(const float4*)(Xb + (size_t)r2 * DD);
        float4 v3 = *(const float4*)(Xb + (size_t)r3 * DD);
        float4 v4 = *(const float4*)(Xb + (size_t)r4 * DD);
        float4 v5 = *(const float4*)(Xb + (size_t)r5 * DD);
        float4 v6 = *(const float4*)(Xb + (size_t)r6 * DD);
        float4 v7 = *(const float4*)(Xb + (size_t)r7 * DD);
        s.x += v0.x; s.y += v0.y; s.z += v0.z; s.w += v0.w;
        s2.x += v1.x; s2.y += v1.y; s2.z += v1.z; s2.w += v1.w;
        s.x += v2.x; s.y += v2.y; s.z += v2.z; s.w += v2.w;
        s2.x += v3.x; s2.y += v3.y; s2.z += v3.z; s2.w += v3.w;
        s.x += v4.x; s.y += v4.y; s.z += v4.z; s.w += v4.w;
        s2.x += v5.x; s2.y += v5.y; s2.z += v5.z; s2.w += v5.w;
        s.x += v6.x; s.y += v6.y; s.z += v6.z; s.w += v6.w;
        s2.x += v7.x; s2.y += v7.y; s2.z += v7.z; s2.w += v7.w;
    }
    for (; i < c; i++) {
        int r = lst[i];
        float4 v = *(const float4*)(Xb + (size_t)r * DD);
        s.x += v.x; s.y += v.y; s.z += v.z; s.w += v.w;
    }
    s.x += s2.x; s.y += s2.y; s.z += s2.z; s.w += s2.w;
    *(float4*)(O + (size_t)g * DD + t * 4) = s;
}

// ---------------- softmax over edge dim + multiply ----------------
__global__ void softmax_edge_kernel(const float* __restrict__ S, float* __restrict__ O)
{
    const int b = blockIdx.y;
    const int tx = threadIdx.x, ty = threadIdx.y;
    const int d = blockIdx.x * 32 + tx;
    __shared__ float sm[32][32];

    const float* Sb = S + (size_t)b * EE * DD + d;
    float mx = -1e30f;
    for (int e = ty; e < EE; e += 32) mx = fmaxf(mx, Sb[(size_t)e * DD]);
    sm[ty][tx] = mx; __syncthreads();
    for (int s = 16; s > 0; s >>= 1) {
        if (ty < s) sm[ty][tx] = fmaxf(sm[ty][tx], sm[ty + s][tx]);
        __syncthreads();
    }
    mx = sm[0][tx]; __syncthreads();

    float sum = 0.f;
    for (int e = ty; e < EE; e += 32) sum += __expf(Sb[(size_t)e * DD] - mx);
    sm[ty][tx] = sum; __syncthreads();
    for (int s = 16; s > 0; s >>= 1) {
        if (ty < s) sm[ty][tx] += sm[ty + s][tx];
        __syncthreads();
    }
    sum = sm[0][tx];

    float inv = 1.f / sum;
    float* Ob = O + (size_t)b * EE * DD + d;
    for (int e = ty; e < EE; e += 32) {
        float v = Sb[(size_t)e * DD];
        Ob[(size_t)e * DD] = v * __expf(v - mx) * inv;
    }
}

// ---------------- reductions ----------------
__device__ __forceinline__ float warp_sum(float v) {
#pragma unroll
    for (int o = 16; o > 0; o >>= 1) v += __shfl_down_sync(0xffffffffu, v, o);
    return v;
}

__device__ __forceinline__ float block_sum256(float v, float* red, float* bc) {
    int lane = threadIdx.x & 31, w = threadIdx.x >> 5;
    float t = warp_sum(v);
    if (lane == 0) red[w] = t;
    __syncthreads();
    if (w == 0) {
        float u = (lane < 8) ? red[lane] : 0.f;
#pragma unroll
        for (int o = 4; o > 0; o >>= 1) u += __shfl_down_sync(0xffffffffu, u, o);
        if (lane == 0) *bc = u;
    }
    __syncthreads();
    return *bc;
}

__global__ void ln_dual_kernel(const float* __restrict__ X, const float* __restrict__ g,
                               const float* __restrict__ bb, const float* __restrict__ p_av,
                               float* __restrict__ Y, float* __restrict__ out_edge)
{
    const int row = blockIdx.x;
    const int d = threadIdx.x;
    __shared__ float red[8];
    __shared__ float bc;

    float x = X[(size_t)row * DD + d];
    float mu = block_sum256(x, red, &bc) * (1.f / DD);
    float dv = x - mu;
    __syncthreads();
    float var = block_sum256(dv * dv, red, &bc) * (1.f / DD);

    float v = dv * rsqrtf(var + LN_EPS) * g[d] + bb[d];
    Y[(size_t)row * DD + d] = v;
    out_edge[(size_t)row * DD + d] = (3.f + *p_av) * v;
}

__global__ void final_node_kernel(const float* __restrict__ Y, const float* __restrict__ feat,
                                  const float* __restrict__ g, const float* __restrict__ bb,
                                  const float* __restrict__ p_av, const float* __restrict__ p_ae,
                                  float* __restrict__ out)
{
    const int row = blockIdx.x;
    const int d = threadIdx.x;
    __shared__ float red[8];
    __shared__ float bc;

    float y = Y[(size_t)row * DD + d];
    float mu = block_sum256(y, red, &bc) * (1.f / DD);
    float z = y - mu;
    __syncthreads();
    float vr = block_sum256(z * z, red, &bc) * (1.f / DD);

    const float ae = *p_ae, av = *p_av;
    const float gd = g[d], bd = bb[d];
    const float c3 = 3.f + av;
    const float t1 = z * rsqrtf(vr + LN_EPS) * gd + bd;
    const float t2 = 2.f * z * rsqrtf(4.f * vr + LN_EPS) * gd + bd;
    const float t3 = c3 * z * rsqrtf(c3 * c3 * vr + LN_EPS) * gd + bd;

    const float op = 1.f + ae;
    out[(size_t)row * DD + d] =
        op * op * op * feat[(size_t)row * DD + d] +
        (1.f - ae) * (op * op * t1 + op * t2 + t3);
}

__global__ void copy4_kernel(const float* __restrict__ in, float* __restrict__ out, int n4)
{
    int i = blockIdx.x * blockDim.x + threadIdx.x;
    if (i < n4) ((float4*)out)[i] = ((const float4*)in)[i];
}

// ---------------- host ----------------
extern "C" void kernel_launch(void* const* d_in, const int* in_sizes, int n_in,
                              void* d_out, int out_size)
{
    const float* feat     = (const float*)d_in[0];
    const float* inc      = (const float*)d_in[1];
    const float* vc_Win   = (const float*)d_in[2];
    const float* vc_bin   = (const float*)d_in[3];
    const float* vc_Wout  = (const float*)d_in[4];
    const float* vc_bout  = (const float*)d_in[5];
    const float* vc_Wproj = (const float*)d_in[6];
    const float* vc_g     = (const float*)d_in[7];
    const float* vc_b     = (const float*)d_in[8];
    const float* vc_alpha = (const float*)d_in[9];
    const float* ec_Wproj = (const float*)d_in[14];
    const float* ec_g     = (const float*)d_in[15];
    const float* ec_b     = (const float*)d_in[16];
    const float* ec_alpha = (const float*)d_in[17];

    float *qkv, *attn, *A, *S, *edge, *Ep, *E0, *Y1, *Y;
    unsigned short *csc_idx, *csr_idx;
    int *csc_cnt, *csr_cnt;
    cudaGetSymbolAddress((void**)&qkv,  g_qkv);
    cudaGetSymbolAddress((void**)&attn, g_attn);
    cudaGetSymbolAddress((void**)&A,    g_A);
    cudaGetSymbolAddress((void**)&S,    g_S);
    cudaGetSymbolAddress((void**)&edge, g_edge);
    cudaGetSymbolAddress((void**)&Ep,   g_Ep);
    cudaGetSymbolAddress((void**)&E0,   g_E0);
    cudaGetSymbolAddress((void**)&Y1,   g_Y1);
    cudaGetSymbolAddress((void**)&Y,    g_Y);
    cudaGetSymbolAddress((void**)&csc_idx, g_csc_idx);
    cudaGetSymbolAddress((void**)&csr_idx, g_csr_idx);
    cudaGetSymbolAddress((void**)&csc_cnt, g_csc_cnt);
    cudaGetSymbolAddress((void**)&csr_cnt, g_csr_cnt);

    const int NODE = BB * MM * DD;
    const int EDGE = BB * EE * DD;
    const int INC  = BB * MM * EE;
    float* out_node = (float*)d_out;
    float* out_edge = out_node + NODE;
    float* out_inc  = out_edge + EDGE;

    // index builds
    csc_build<<<(BB * EE + 255) / 256, 256>>>(inc);
    csr_build<<<(BB * MM * 32 + 255) / 256, 256>>>(inc);

    // 1) QKV = feat @ vc_Win^T + vc_bin       [8192 x 768]
    gemm_mma<true><<<dim3(6, 64), 256>>>(feat, vc_Win, vc_bin, qkv, 8192, 768, 256);

    // 2) attention (tf32 mma, 2x q-blocked)
    attn_mma<<<dim3(BB * HH, 4), 256>>>(qkv, attn);

    // 3) A = attn @ vc_Wout^T + vc_bout       [8192 x 256]
    gemm_mma<true><<<dim3(2, 64), 256>>>(attn, vc_Wout, vc_bout, A, 8192, 256, 256);

    // 4) S[b,e,:] = sum_m inc[b,m,e] * A[b,m,:]
    spmm_gather<<<BB * EE / 4, 256>>>(csc_idx, csc_cnt, A, S, EE, MM);

    // 5) edge = S * softmax_e(S)
    softmax_edge_kernel<<<dim3(DD / 32, BB), dim3(32, 32)>>>(S, edge);

    // 6) Ep = edge @ vc_Wproj^T               [12288 x 256]
    gemm_mma<false><<<dim3(2, 96), 256>>>(edge, vc_Wproj, nullptr, Ep, 12288, 256, 256);

    // 7) E0 = LN(Ep); out_edge = (3+av)*E0
    ln_dual_kernel<<<BB * EE, DD>>>(Ep, vc_g, vc_b, vc_alpha, E0, out_edge);

    // 8) Y1[b,m,:] = sum_e inc[b,m,e] * E0[b,e,:]
    spmm_gather<<<BB * MM / 4, 256>>>(csr_idx, csr_cnt, E0, Y1, MM, EE);

    // 9) Y = Y1 @ ec_Wproj^T                  [8192 x 256]
    gemm_mma<false><<<dim3(2, 64), 256>>>(Y1, ec_Wproj, nullptr, Y, 8192, 256, 256);

    // 10) node output
    final_node_kernel<<<BB * MM, DD>>>(Y, feat, ec_g, ec_b, vc_alpha, ec_alpha, out_node);

    // 11) inc passthrough
    if (out_size >= NODE + EDGE + INC) {
        int n4 = INC / 4;
        copy4_kernel<<<(n4 + 255) / 256, 256>>>(inc, out_inc, n4);
    }
}

// round 7
// speedup vs baseline: 3.3845x; 1.1966x over previous
#include <cuda_runtime.h>
#include <math.h>

#define BB 8
#define MM 1024
#define EE 1536
#define DD 256
#define HH 8
#define LN_EPS 1e-5f
#define CAP 256

// ---------------- scratch ----------------
__device__ float g_qkv[BB*MM*3*DD];
__device__ float g_attn[BB*MM*DD];
__device__ float g_A[BB*MM*DD];
__device__ float g_S[BB*EE*DD];
__device__ float g_Ep[BB*EE*DD];
__device__ float g_Y1[BB*MM*DD];
__device__ float g_Y[BB*MM*DD];
__device__ float g_inv[BB*DD];
__device__ unsigned short g_csc_idx[(size_t)BB*EE*CAP];
__device__ int            g_csc_cnt[BB*EE];
__device__ unsigned short g_csr_idx[(size_t)BB*MM*CAP];
__device__ int            g_csr_cnt[BB*MM];

// ---------------- tf32 mma helpers ----------------
__device__ __forceinline__ unsigned tf32c(float f) {
    unsigned r;
    asm("cvt.rna.tf32.f32 %0, %1;" : "=r"(r) : "f"(f));
    return r;
}
__device__ __forceinline__ void mma_tf32(float4& d, unsigned a0, unsigned a1,
                                         unsigned a2, unsigned a3,
                                         unsigned b0, unsigned b1) {
    asm volatile(
        "mma.sync.aligned.m16n8k8.row.col.f32.tf32.tf32.f32 "
        "{%0,%1,%2,%3}, {%4,%5,%6,%7}, {%8,%9}, {%0,%1,%2,%3};"
        : "+f"(d.x), "+f"(d.y), "+f"(d.z), "+f"(d.w)
        : "r"(a0), "r"(a1), "r"(a2), "r"(a3), "r"(b0), "r"(b1));
}

// ---------------- dense GEMM body (device fn): C = A[M,K] @ W[N,K]^T (+bias) ----------------
// SOFTW: A-load computes on-the-fly  a = S * exp(S) * inv[b][k]   (edge weighting)
template<bool BIAS, bool SOFTW>
__device__ __forceinline__ void
gemm_body(const float* __restrict__ A, const float* __restrict__ W,
          const float* __restrict__ bias, float* __restrict__ C,
          int Ndim, int Kdim, const float* __restrict__ invp,
          int bx, int by)
{
    const int m0 = by * 128;
    const int n0 = bx * 128;
    const int tid = threadIdx.x;
    const int warp = tid >> 5, lane = tid & 31;
    const int wr = warp >> 2, wc = warp & 3;
    const int g = lane >> 2, t = lane & 3;
    const int bb0 = m0 / EE;   // batch index (valid when SOFTW; blocks never straddle b)

    __shared__ unsigned As[128 * 36];
    __shared__ unsigned Bs[128 * 36];

    float4 acc[4][4];
#pragma unroll
    for (int i = 0; i < 4; i++)
#pragma unroll
        for (int j = 0; j < 4; j++) acc[i][j] = make_float4(0.f, 0.f, 0.f, 0.f);

    const int lr = tid >> 3;
    const int lc = (tid & 7) * 4;

    for (int kt = 0; kt < Kdim; kt += 32) {
#pragma unroll
        for (int p = 0; p < 4; p++) {
            int r = lr + p * 32;
            float4 va = *(const float4*)(A + (size_t)(m0 + r) * Kdim + kt + lc);
            if (SOFTW) {
                float4 vi = *(const float4*)(invp + bb0 * DD + kt + lc);
                va.x = va.x * __expf(va.x) * vi.x;
                va.y = va.y * __expf(va.y) * vi.y;
                va.z = va.z * __expf(va.z) * vi.z;
                va.w = va.w * __expf(va.w) * vi.w;
            }
            float4 vb = *(const float4*)(W + (size_t)(n0 + r) * Kdim + kt + lc);
            uint4 ua = make_uint4(tf32c(va.x), tf32c(va.y), tf32c(va.z), tf32c(va.w));
            uint4 ub = make_uint4(tf32c(vb.x), tf32c(vb.y), tf32c(vb.z), tf32c(vb.w));
            *(uint4*)&As[r * 36 + lc] = ua;
            *(uint4*)&Bs[r * 36 + lc] = ub;
        }
        __syncthreads();
#pragma unroll
        for (int ks = 0; ks < 4; ks++) {
            const int k0 = ks * 8;
            unsigned af[4][4];
#pragma unroll
            for (int ms = 0; ms < 4; ms++) {
                int row = wr * 64 + ms * 16 + g;
                af[ms][0] = As[row * 36 + k0 + t];
                af[ms][1] = As[(row + 8) * 36 + k0 + t];
                af[ms][2] = As[row * 36 + k0 + 4 + t];
                af[ms][3] = As[(row + 8) * 36 + k0 + 4 + t];
            }
            unsigned bf[4][2];
#pragma unroll
            for (int ns = 0; ns < 4; ns++) {
                int nrow = wc * 32 + ns * 8 + g;
                bf[ns][0] = Bs[nrow * 36 + k0 + t];
                bf[ns][1] = Bs[nrow * 36 + k0 + 4 + t];
            }
#pragma unroll
            for (int ms = 0; ms < 4; ms++)
#pragma unroll
                for (int ns = 0; ns < 4; ns++)
                    mma_tf32(acc[ms][ns], af[ms][0], af[ms][1], af[ms][2], af[ms][3],
                             bf[ns][0], bf[ns][1]);
        }
        __syncthreads();
    }

#pragma unroll
    for (int ms = 0; ms < 4; ms++) {
        int r0 = m0 + wr * 64 + ms * 16 + g;
#pragma unroll
        for (int ns = 0; ns < 4; ns++) {
            int col = n0 + wc * 32 + ns * 8 + t * 2;
            float bx2 = 0.f, by2 = 0.f;
            if (BIAS) { bx2 = bias[col]; by2 = bias[col + 1]; }
            float2 v0 = make_float2(acc[ms][ns].x + bx2, acc[ms][ns].y + by2);
            float2 v1 = make_float2(acc[ms][ns].z + bx2, acc[ms][ns].w + by2);
            *(float2*)(C + (size_t)r0 * Ndim + col)       = v0;
            *(float2*)(C + (size_t)(r0 + 8) * Ndim + col) = v1;
        }
    }
}

template<bool BIAS, bool SOFTW>
__global__ void __launch_bounds__(256)
gemm_mma(const float* __restrict__ A, const float* __restrict__ W,
         const float* __restrict__ bias, float* __restrict__ C,
         int Ndim, int Kdim, const float* __restrict__ invp)
{
    gemm_body<BIAS, SOFTW>(A, W, bias, C, Ndim, Kdim, invp, blockIdx.x, blockIdx.y);
}

// ---------------- stage1 fat kernel: QKV gemm + csc/csr builds + inc copy ----------------
// block ranges: [0,384) gemm 6x64 | [384,432) csc | [432,1456) csr | [1456,2480) copy
#define S1_GEMM 384
#define S1_CSC  (S1_GEMM + 48)
#define S1_CSR  (S1_CSC + 1024)
#define S1_TOT  (S1_CSR + 1024)

__global__ void __launch_bounds__(256)
stage1(const float* __restrict__ feat, const float* __restrict__ Win,
       const float* __restrict__ bin, float* __restrict__ qkv,
       const float* __restrict__ inc, float* __restrict__ out_inc, int do_copy)
{
    const int bid = blockIdx.x;
    const int tid = threadIdx.x;

    if (bid < S1_GEMM) {
        gemm_body<true, false>(feat, Win, bin, qkv, 768, 256, nullptr, bid % 6, bid / 6);
    } else if (bid < S1_CSC) {
        // CSC: one thread per (b,e)
        int ge = (bid - S1_GEMM) * 256 + tid;
        int b = ge / EE, e = ge % EE;
        const float* p = inc + (size_t)b * MM * EE + e;
        unsigned short* lst = g_csc_idx + (size_t)ge * CAP;
        int cnt = 0;
        for (int m = 0; m < MM; m++) {
            if (p[(size_t)m * EE] != 0.f) {
                if (cnt < CAP) lst[cnt] = (unsigned short)m;
                cnt++;
            }
        }
        g_csc_cnt[ge] = cnt < CAP ? cnt : CAP;
    } else if (bid < S1_CSR) {
        // CSR: one warp per (b,m)
        int wid = ((bid - S1_CSC) * 256 + tid) >> 5;
        int lane = tid & 31;
        const float* p = inc + (size_t)wid * EE;
        unsigned short* lst = g_csr_idx + (size_t)wid * CAP;
        int cnt = 0;
        for (int eb = 0; eb < EE; eb += 32) {
            float v = p[eb + lane];
            unsigned mask = __ballot_sync(0xffffffffu, v != 0.f);
            if (v != 0.f) {
                int pos = cnt + __popc(mask & ((1u << lane) - 1u));
                if (pos < CAP) lst[pos] = (unsigned short)(eb + lane);
            }
            cnt += __popc(mask);
        }
        if (lane == 0) g_csr_cnt[wid] = cnt < CAP ? cnt : CAP;
    } else if (do_copy) {
        // inc passthrough, grid-stride float4 copy
        const int n4 = BB * MM * EE / 4;
        const int stride = 1024 * 256;
        for (int i = (bid - S1_CSR) * 256 + tid; i < n4; i += stride)
            ((float4*)out_inc)[i] = ((const float4*)inc)[i];
    }
}

// ---------------- attention via tf32 mma (dh=32), 2x q-blocking ----------------
__global__ void __launch_bounds__(256, 2)
attn_mma(const float* __restrict__ qkv, float* __restrict__ out)
{
    const int bh = blockIdx.x;
    const int b = bh >> 3, h = bh & 7;
    const int tid = threadIdx.x;
    const int warp = tid >> 5, lane = tid & 31;
    const int g = lane >> 2, t = lane & 3;
    const int qw = blockIdx.y * 256 + warp * 32;

    __shared__ unsigned Ks[64 * 36];
    __shared__ unsigned Vs[64 * 40];

    const float scale = 0.17677669529663687f;
    unsigned qf[2][4][4];
#pragma unroll
    for (int qt = 0; qt < 2; qt++) {
        const float* q0 = qkv + (size_t)(b * MM + qw + qt * 16 + g) * 768 + h * 32;
        const float* q1 = qkv + (size_t)(b * MM + qw + qt * 16 + g + 8) * 768 + h * 32;
#pragma unroll
        for (int ks = 0; ks < 4; ks++) {
            qf[qt][ks][0] = tf32c(q0[ks * 8 + t] * scale);
            qf[qt][ks][1] = tf32c(q1[ks * 8 + t] * scale);
            qf[qt][ks][2] = tf32c(q0[ks * 8 + 4 + t] * scale);
            qf[qt][ks][3] = tf32c(q1[ks * 8 + 4 + t] * scale);
        }
    }

    float4 o0[4], o1[4];
#pragma unroll
    for (int i = 0; i < 4; i++) {
        o0[i] = make_float4(0.f, 0.f, 0.f, 0.f);
        o1[i] = make_float4(0.f, 0.f, 0.f, 0.f);
    }
    float l00 = 0.f, l01 = 0.f, l10 = 0.f, l11 = 0.f;

    const int lr = tid >> 3;
    const int lc = (tid & 7) * 4;
    const unsigned fullm = 0xffffffffu;
    const int src0 = (lane & 28) | (t >> 1);
    const int src2 = src0 + 2;
    const bool odd = (t & 1);

    for (int ch = 0; ch < 16; ch++) {
        const int kbase = ch * 64;
#pragma unroll
        for (int p = 0; p < 2; p++) {
            int r = lr + p * 32;
            const float* src = qkv + (size_t)(b * MM + kbase + r) * 768 + h * 32 + lc;
            float4 vk = *(const float4*)(src + 256);
            float4 vv = *(const float4*)(src + 512);
            *(uint4*)&Ks[r * 36 + lc] = make_uint4(tf32c(vk.x), tf32c(vk.y), tf32c(vk.z), tf32c(vk.w));
            *(uint4*)&Vs[r * 40 + lc] = make_uint4(tf32c(vv.x), tf32c(vv.y), tf32c(vv.z), tf32c(vv.w));
        }
        __syncthreads();

#pragma unroll
        for (int ns = 0; ns < 8; ns++) {
            float4 s0 = make_float4(0.f, 0.f, 0.f, 0.f);
            float4 s1 = make_float4(0.f, 0.f, 0.f, 0.f);
#pragma unroll
            for (int ks = 0; ks < 4; ks++) {
                int nrow = ns * 8 + g;
                unsigned b0 = Ks[nrow * 36 + ks * 8 + t];
                unsigned b1 = Ks[nrow * 36 + ks * 8 + 4 + t];
                mma_tf32(s0, qf[0][ks][0], qf[0][ks][1], qf[0][ks][2], qf[0][ks][3], b0, b1);
                mma_tf32(s1, qf[1][ks][0], qf[1][ks][1], qf[1][ks][2], qf[1][ks][3], b0, b1);
            }
            s0.x = __expf(s0.x); s0.y = __expf(s0.y); s0.z = __expf(s0.z); s0.w = __expf(s0.w);
            s1.x = __expf(s1.x); s1.y = __expf(s1.y); s1.z = __expf(s1.z); s1.w = __expf(s1.w);
            l00 += s0.x + s0.y; l01 += s0.z + s0.w;
            l10 += s1.x + s1.y; l11 += s1.z + s1.w;

            float ax0 = __shfl_sync(fullm, s0.x, src0);
            float ay0 = __shfl_sync(fullm, s0.y, src0);
            float az0 = __shfl_sync(fullm, s0.z, src0);
            float aw0 = __shfl_sync(fullm, s0.w, src0);
            float ax2 = __shfl_sync(fullm, s0.x, src2);
            float ay2 = __shfl_sync(fullm, s0.y, src2);
            float az2 = __shfl_sync(fullm, s0.z, src2);
            float aw2 = __shfl_sync(fullm, s0.w, src2);
            unsigned pa0 = tf32c(odd ? ay0 : ax0);
            unsigned pa1 = tf32c(odd ? aw0 : az0);
            unsigned pa2 = tf32c(odd ? ay2 : ax2);
            unsigned pa3 = tf32c(odd ? aw2 : az2);

            float bx0 = __shfl_sync(fullm, s1.x, src0);
            float by0 = __shfl_sync(fullm, s1.y, src0);
            float bz0 = __shfl_sync(fullm, s1.z, src0);
            float bw0 = __shfl_sync(fullm, s1.w, src0);
            float bx2 = __shfl_sync(fullm, s1.x, src2);
            float by2 = __shfl_sync(fullm, s1.y, src2);
            float bz2 = __shfl_sync(fullm, s1.z, src2);
            float bw2 = __shfl_sync(fullm, s1.w, src2);
            unsigned pb0 = tf32c(odd ? by0 : bx0);
            unsigned pb1 = tf32c(odd ? bw0 : bz0);
            unsigned pb2 = tf32c(odd ? by2 : bx2);
            unsigned pb3 = tf32c(odd ? bw2 : bz2);

#pragma unroll
            for (int ds = 0; ds < 4; ds++) {
                unsigned v0 = Vs[(ns * 8 + t) * 40 + ds * 8 + g];
                unsigned v1 = Vs[(ns * 8 + 4 + t) * 40 + ds * 8 + g];
                mma_tf32(o0[ds], pa0, pa1, pa2, pa3, v0, v1);
                mma_tf32(o1[ds], pb0, pb1, pb2, pb3, v0, v1);
            }
        }
        __syncthreads();
    }

    l00 += __shfl_xor_sync(fullm, l00, 1); l00 += __shfl_xor_sync(fullm, l00, 2);
    l01 += __shfl_xor_sync(fullm, l01, 1); l01 += __shfl_xor_sync(fullm, l01, 2);
    l10 += __shfl_xor_sync(fullm, l10, 1); l10 += __shfl_xor_sync(fullm, l10, 2);
    l11 += __shfl_xor_sync(fullm, l11, 1); l11 += __shfl_xor_sync(fullm, l11, 2);
    float i00 = 1.f / l00, i01 = 1.f / l01;
    float i10 = 1.f / l10, i11 = 1.f / l11;

    {
        float* p0 = out + (size_t)(b * MM + qw + g) * DD + h * 32;
        float* p1 = out + (size_t)(b * MM + qw + g + 8) * DD + h * 32;
#pragma unroll
        for (int ds = 0; ds < 4; ds++) {
            int col = ds * 8 + t * 2;
            *(float2*)(p0 + col) = make_float2(o0[ds].x * i00, o0[ds].y * i00);
            *(float2*)(p1 + col) = make_float2(o0[ds].z * i01, o0[ds].w * i01);
        }
        float* p2 = out + (size_t)(b * MM + qw + 16 + g) * DD + h * 32;
        float* p3 = out + (size_t)(b * MM + qw + 16 + g + 8) * DD + h * 32;
#pragma unroll
        for (int ds = 0; ds < 4; ds++) {
            int col = ds * 8 + t * 2;
            *(float2*)(p2 + col) = make_float2(o1[ds].x * i10, o1[ds].y * i10);
            *(float2*)(p3 + col) = make_float2(o1[ds].z * i11, o1[ds].w * i11);
        }
    }
}

// ---------------- sparse aggregation (unroll 8). SCALE: multiply by 1/(3+*sc) ----------------
template<bool SCALE>
__global__ void __launch_bounds__(256)
spmm_gather(const unsigned short* __restrict__ idx, const int* __restrict__ cnt,
            const float* __restrict__ X, float* __restrict__ O,
            int groups_per_b, int rows_per_b, const float* __restrict__ sc)
{
    int g = blockIdx.x * 4 + (threadIdx.x >> 6);
    int b = g / groups_per_b;
    int t = threadIdx.x & 63;
    int c = cnt[g];
    const unsigned short* lst = idx + (size_t)g * CAP;
    const float* Xb = X + (size_t)b * rows_per_b * DD + t * 4;
    float4 s = make_float4(0.f, 0.f, 0.f, 0.f);
    float4 s2 = make_float4(0.f, 0.f, 0.f, 0.f);
    int i = 0;
    for (; i + 8 <= c; i += 8) {
        int r0 = lst[i], r1 = lst[i+1], r2 = lst[i+2], r3 = lst[i+3];
        int r4 = lst[i+4], r5 = lst[i+5], r6 = lst[i+6], r7 = lst[i+7];
        float4 v0 = *(const float4*)(Xb + (size_t)r0 * DD);
        float4 v1 = *(const float4*)(Xb + (size_t)r1 * DD);
        float4 v2 = *(const float4*)(Xb + (size_t)r2 * DD);
        float4 v3 = *(const float4*)(Xb + (size_t)r3 * DD);
        float4 v4 = *(const float4*)(Xb + (size_t)r4 * DD);
        float4 v5 = *(const float4*)(Xb + (size_t)r5 * DD);
        float4 v6 = *(const float4*)(Xb + (size_t)r6 * DD);
        float4 v7 = *(const float4*)(Xb + (size_t)r7 * DD);
        s.x += v0.x; s.y += v0.y; s.z += v0.z; s.w += v0.w;
        s2.x += v1.x; s2.y += v1.y; s2.z += v1.z; s2.w += v1.w;
        s.x += v2.x; s.y += v2.y; s.z += v2.z; s.w += v2.w;
        s2.x += v3.x; s2.y += v3.y; s2.z += v3.z; s2.w += v3.w;
        s.x += v4.x; s.y += v4.y; s.z += v4.z; s.w += v4.w;
        s2.x += v5.x; s2.y += v5.y; s2.z += v5.z; s2.w += v5.w;
        s.x += v6.x; s.y += v6.y; s.z += v6.z; s.w += v6.w;
        s2.x += v7.x; s2.y += v7.y; s2.z += v7.z; s2.w += v7.w;
    }
    for (; i < c; i++) {
        int r = lst[i];
        float4 v = *(const float4*)(Xb + (size_t)r * DD);
        s.x += v.x; s.y += v.y; s.z += v.z; s.w += v.w;
    }
    s.x += s2.x; s.y += s2.y; s.z += s2.z; s.w += s2.w;
    if (SCALE) {
        float f = 1.f / (3.f + *sc);
        s.x *= f; s.y *= f; s.z *= f; s.w *= f;
    }
    *(float4*)(O + (size_t)g * DD + t * 4) = s;
}

// ---------------- softmax stats: inv[b,d] = 1 / sum_e exp(S[b,e,d]) ----------------
__global__ void softmax_stats(const float* __restrict__ S, float* __restrict__ invp)
{
    const int b = blockIdx.y;
    const int tx = threadIdx.x, ty = threadIdx.y;
    const int d = blockIdx.x * 32 + tx;
    __shared__ float sm[32][33];

    const float* Sb = S + (size_t)b * EE * DD + d;
    float sum = 0.f;
    for (int e = ty; e < EE; e += 32) sum += __expf(Sb[(size_t)e * DD]);
    sm[ty][tx] = sum; __syncthreads();
    for (int s = 16; s > 0; s >>= 1) {
        if (ty < s) sm[ty][tx] += sm[ty + s][tx];
        __syncthreads();
    }
    if (ty == 0) invp[b * DD + d] = 1.f / sm[0][tx];
}

// ---------------- reductions ----------------
__device__ __forceinline__ float warp_sum(float v) {
#pragma unroll
    for (int o = 16; o > 0; o >>= 1) v += __shfl_down_sync(0xffffffffu, v, o);
    return v;
}

__device__ __forceinline__ float block_sum256(float v, float* red, float* bc) {
    int lane = threadIdx.x & 31, w = threadIdx.x >> 5;
    float t = warp_sum(v);
    if (lane == 0) red[w] = t;
    __syncthreads();
    if (w == 0) {
        float u = (lane < 8) ? red[lane] : 0.f;
#pragma unroll
        for (int o = 4; o > 0; o >>= 1) u += __shfl_down_sync(0xffffffffu, u, o);
        if (lane == 0) *bc = u;
    }
    __syncthreads();
    return *bc;
}

// LN -> out_edge = (3+av) * LN(X)
__global__ void ln_edge_kernel(const float* __restrict__ X, const float* __restrict__ g,
                               const float* __restrict__ bb, const float* __restrict__ p_av,
                               float* __restrict__ out_edge)
{
    const int row = blockIdx.x;
    const int d = threadIdx.x;
    __shared__ float red[8];
    __shared__ float bc;

    float x = X[(size_t)row * DD + d];
    float mu = block_sum256(x, red, &bc) * (1.f / DD);
    float dv = x - mu;
    __syncthreads();
    float var = block_sum256(dv * dv, red, &bc) * (1.f / DD);

    float v = dv * rsqrtf(var + LN_EPS) * g[d] + bb[d];
    out_edge[(size_t)row * DD + d] = (3.f + *p_av) * v;
}

__global__ void final_node_kernel(const float* __restrict__ Y, const float* __restrict__ feat,
                                  const float* __restrict__ g, const float* __restrict__ bb,
                                  const float* __restrict__ p_av, const float* __restrict__ p_ae,
                                  float* __restrict__ out)
{
    const int row = blockIdx.x;
    const int d = threadIdx.x;
    __shared__ float red[8];
    __shared__ float bc;

    float y = Y[(size_t)row * DD + d];
    float mu = block_sum256(y, red, &bc) * (1.f / DD);
    float z = y - mu;
    __syncthreads();
    float vr = block_sum256(z * z, red, &bc) * (1.f / DD);

    const float ae = *p_ae, av = *p_av;
    const float gd = g[d], bd = bb[d];
    const float c3 = 3.f + av;
    const float t1 = z * rsqrtf(vr + LN_EPS) * gd + bd;
    const float t2 = 2.f * z * rsqrtf(4.f * vr + LN_EPS) * gd + bd;
    const float t3 = c3 * z * rsqrtf(c3 * c3 * vr + LN_EPS) * gd + bd;

    const float op = 1.f + ae;
    out[(size_t)row * DD + d] =
        op * op * op * feat[(size_t)row * DD + d] +
        (1.f - ae) * (op * op * t1 + op * t2 + t3);
}

// ---------------- host ----------------
extern "C" void kernel_launch(void* const* d_in, const int* in_sizes, int n_in,
                              void* d_out, int out_size)
{
    const float* feat     = (const float*)d_in[0];
    const float* inc      = (const float*)d_in[1];
    const float* vc_Win   = (const float*)d_in[2];
    const float* vc_bin   = (const float*)d_in[3];
    const float* vc_Wout  = (const float*)d_in[4];
    const float* vc_bout  = (const float*)d_in[5];
    const float* vc_Wproj = (const float*)d_in[6];
    const float* vc_g     = (const float*)d_in[7];
    const float* vc_b     = (const float*)d_in[8];
    const float* vc_alpha = (const float*)d_in[9];
    const float* ec_Wproj = (const float*)d_in[14];
    const float* ec_g     = (const float*)d_in[15];
    const float* ec_b     = (const float*)d_in[16];
    const float* ec_alpha = (const float*)d_in[17];

    float *qkv, *attn, *A, *S, *Ep, *Y1, *Y, *invp;
    unsigned short *csc_idx, *csr_idx;
    int *csc_cnt, *csr_cnt;
    cudaGetSymbolAddress((void**)&qkv,  g_qkv);
    cudaGetSymbolAddress((void**)&attn, g_attn);
    cudaGetSymbolAddress((void**)&A,    g_A);
    cudaGetSymbolAddress((void**)&S,    g_S);
    cudaGetSymbolAddress((void**)&Ep,   g_Ep);
    cudaGetSymbolAddress((void**)&Y1,   g_Y1);
    cudaGetSymbolAddress((void**)&Y,    g_Y);
    cudaGetSymbolAddress((void**)&invp, g_inv);
    cudaGetSymbolAddress((void**)&csc_idx, g_csc_idx);
    cudaGetSymbolAddress((void**)&csr_idx, g_csr_idx);
    cudaGetSymbolAddress((void**)&csc_cnt, g_csc_cnt);
    cudaGetSymbolAddress((void**)&csr_cnt, g_csr_cnt);

    const int NODE = BB * MM * DD;
    const int EDGE = BB * EE * DD;
    const int INC  = BB * MM * EE;
    float* out_node = (float*)d_out;
    float* out_edge = out_node + NODE;
    float* out_inc  = out_edge + EDGE;
    const int do_copy = (out_size >= NODE + EDGE + INC) ? 1 : 0;

    // 1) fat kernel: QKV gemm + csc/csr index builds + inc passthrough copy
    stage1<<<S1_TOT, 256>>>(feat, vc_Win, vc_bin, qkv, inc, out_inc, do_copy);

    // 2) attention (tf32 mma, 2x q-blocked)
    attn_mma<<<dim3(BB * HH, 4), 256>>>(qkv, attn);

    // 3) A = attn @ vc_Wout^T + vc_bout
    gemm_mma<true, false><<<dim3(2, 64), 256>>>(attn, vc_Wout, vc_bout, A, 256, 256, nullptr);

    // 4) S[b,e,:] = sum_m inc[b,m,e] * A[b,m,:]
    spmm_gather<false><<<BB * EE / 4, 256>>>(csc_idx, csc_cnt, A, S, EE, MM, nullptr);

    // 5) inv[b,d] = 1 / sum_e exp(S)
    softmax_stats<<<dim3(DD / 32, BB), dim3(32, 32)>>>(S, invp);

    // 6) Ep = (S * exp(S) * inv) @ vc_Wproj^T   (edge weighting fused in A-load)
    gemm_mma<false, true><<<dim3(2, 96), 256>>>(S, vc_Wproj, nullptr, Ep, 256, 256, invp);

    // 7) out_edge = (3+av) * LN(Ep)
    ln_edge_kernel<<<BB * EE, DD>>>(Ep, vc_g, vc_b, vc_alpha, out_edge);

    // 8) Y1[b,m,:] = sum_e inc[b,m,e] * E0[b,e,:]  (E0 = out_edge / (3+av))
    spmm_gather<true><<<BB * MM / 4, 256>>>(csr_idx, csr_cnt, out_edge, Y1, MM, EE, vc_alpha);

    // 9) Y = Y1 @ ec_Wproj^T
    gemm_mma<false, false><<<dim3(2, 64), 256>>>(Y1, ec_Wproj, nullptr, Y, 256, 256, nullptr);

    // 10) node output
    final_node_kernel<<<BB * MM, DD>>>(Y, feat, ec_g, ec_b, vc_alpha, ec_alpha, out_node);
}

// round 8
// speedup vs baseline: 3.8998x; 1.1523x over previous
#include <cuda_runtime.h>
#include <math.h>

#define BB 8
#define MM 1024
#define EE 1536
#define DD 256
#define HH 8
#define LN_EPS 1e-5f
#define CAP 256

// ---------------- scratch ----------------
__device__ float g_qkv[BB*MM*3*DD];
__device__ float g_attn[BB*MM*DD];
__device__ float g_A[BB*MM*DD];
__device__ float g_S[BB*EE*DD];
__device__ float g_Ep[BB*EE*DD];
__device__ float g_Y1[BB*MM*DD];
__device__ float g_Y[BB*MM*DD];
__device__ float g_sum[BB*DD];          // column sums of exp(S), atomically accumulated
__device__ unsigned short g_csc_idx[(size_t)BB*EE*CAP];
__device__ int            g_csc_cnt[BB*EE];
__device__ unsigned short g_csr_idx[(size_t)BB*MM*CAP];
__device__ int            g_csr_cnt[BB*MM];

// ---------------- tf32 mma helpers ----------------
__device__ __forceinline__ unsigned tf32c(float f) {
    unsigned r;
    asm("cvt.rna.tf32.f32 %0, %1;" : "=r"(r) : "f"(f));
    return r;
}
__device__ __forceinline__ void mma_tf32(float4& d, unsigned a0, unsigned a1,
                                         unsigned a2, unsigned a3,
                                         unsigned b0, unsigned b1) {
    asm volatile(
        "mma.sync.aligned.m16n8k8.row.col.f32.tf32.tf32.f32 "
        "{%0,%1,%2,%3}, {%4,%5,%6,%7}, {%8,%9}, {%0,%1,%2,%3};"
        : "+f"(d.x), "+f"(d.y), "+f"(d.z), "+f"(d.w)
        : "r"(a0), "r"(a1), "r"(a2), "r"(a3), "r"(b0), "r"(b1));
}

// ---------------- dense GEMM: C = A[M,K] @ W[N,K]^T (+bias) ----------------
// SOFTW: A-load computes  a = S * exp(S) / colsum[b][k]  (edge weighting; recip cached in smem)
template<bool BIAS, bool SOFTW>
__global__ void __launch_bounds__(256)
gemm_mma(const float* __restrict__ A, const float* __restrict__ W,
         const float* __restrict__ bias, float* __restrict__ C,
         int Ndim, int Kdim, const float* __restrict__ sump)
{
    const int m0 = blockIdx.y * 128;
    const int n0 = blockIdx.x * 128;
    const int tid = threadIdx.x;
    const int warp = tid >> 5, lane = tid & 31;
    const int wr = warp >> 2, wc = warp & 3;
    const int g = lane >> 2, t = lane & 3;
    const int bb0 = m0 / EE;   // batch index (valid when SOFTW; blocks never straddle b)

    __shared__ unsigned As[128 * 36];
    __shared__ unsigned Bs[128 * 36];
    __shared__ float sinv[256];

    if (SOFTW) {
        sinv[tid] = 1.f / sump[bb0 * DD + tid];
        __syncthreads();
    }

    float4 acc[4][4];
#pragma unroll
    for (int i = 0; i < 4; i++)
#pragma unroll
        for (int j = 0; j < 4; j++) acc[i][j] = make_float4(0.f, 0.f, 0.f, 0.f);

    const int lr = tid >> 3;
    const int lc = (tid & 7) * 4;

    for (int kt = 0; kt < Kdim; kt += 32) {
#pragma unroll
        for (int p = 0; p < 4; p++) {
            int r = lr + p * 32;
            float4 va = *(const float4*)(A + (size_t)(m0 + r) * Kdim + kt + lc);
            if (SOFTW) {
                va.x = va.x * __expf(va.x) * sinv[kt + lc];
                va.y = va.y * __expf(va.y) * sinv[kt + lc + 1];
                va.z = va.z * __expf(va.z) * sinv[kt + lc + 2];
                va.w = va.w * __expf(va.w) * sinv[kt + lc + 3];
            }
            float4 vb = *(const float4*)(W + (size_t)(n0 + r) * Kdim + kt + lc);
            uint4 ua = make_uint4(tf32c(va.x), tf32c(va.y), tf32c(va.z), tf32c(va.w));
            uint4 ub = make_uint4(tf32c(vb.x), tf32c(vb.y), tf32c(vb.z), tf32c(vb.w));
            *(uint4*)&As[r * 36 + lc] = ua;
            *(uint4*)&Bs[r * 36 + lc] = ub;
        }
        __syncthreads();
#pragma unroll
        for (int ks = 0; ks < 4; ks++) {
            const int k0 = ks * 8;
            unsigned af[4][4];
#pragma unroll
            for (int ms = 0; ms < 4; ms++) {
                int row = wr * 64 + ms * 16 + g;
                af[ms][0] = As[row * 36 + k0 + t];
                af[ms][1] = As[(row + 8) * 36 + k0 + t];
                af[ms][2] = As[row * 36 + k0 + 4 + t];
                af[ms][3] = As[(row + 8) * 36 + k0 + 4 + t];
            }
            unsigned bf[4][2];
#pragma unroll
            for (int ns = 0; ns < 4; ns++) {
                int nrow = wc * 32 + ns * 8 + g;
                bf[ns][0] = Bs[nrow * 36 + k0 + t];
                bf[ns][1] = Bs[nrow * 36 + k0 + 4 + t];
            }
#pragma unroll
            for (int ms = 0; ms < 4; ms++)
#pragma unroll
                for (int ns = 0; ns < 4; ns++)
                    mma_tf32(acc[ms][ns], af[ms][0], af[ms][1], af[ms][2], af[ms][3],
                             bf[ns][0], bf[ns][1]);
        }
        __syncthreads();
    }

#pragma unroll
    for (int ms = 0; ms < 4; ms++) {
        int r0 = m0 + wr * 64 + ms * 16 + g;
#pragma unroll
        for (int ns = 0; ns < 4; ns++) {
            int col = n0 + wc * 32 + ns * 8 + t * 2;
            float bx2 = 0.f, by2 = 0.f;
            if (BIAS) { bx2 = bias[col]; by2 = bias[col + 1]; }
            float2 v0 = make_float2(acc[ms][ns].x + bx2, acc[ms][ns].y + by2);
            float2 v1 = make_float2(acc[ms][ns].z + bx2, acc[ms][ns].w + by2);
            *(float2*)(C + (size_t)r0 * Ndim + col)       = v0;
            *(float2*)(C + (size_t)(r0 + 8) * Ndim + col) = v1;
        }
    }
}

// ---------------- attention body (device fn, dh=32, 2x q-blocking) ----------------
__device__ __forceinline__ void
attn_body(const float* __restrict__ qkv, float* __restrict__ out,
          int bh, int qt, unsigned* Ks, unsigned* Vs)
{
    const int b = bh >> 3, h = bh & 7;
    const int tid = threadIdx.x;
    const int warp = tid >> 5, lane = tid & 31;
    const int g = lane >> 2, t = lane & 3;
    const int qw = qt * 256 + warp * 32;

    const float scale = 0.17677669529663687f;
    unsigned qf[2][4][4];
#pragma unroll
    for (int q2 = 0; q2 < 2; q2++) {
        const float* q0 = qkv + (size_t)(b * MM + qw + q2 * 16 + g) * 768 + h * 32;
        const float* q1 = qkv + (size_t)(b * MM + qw + q2 * 16 + g + 8) * 768 + h * 32;
#pragma unroll
        for (int ks = 0; ks < 4; ks++) {
            qf[q2][ks][0] = tf32c(q0[ks * 8 + t] * scale);
            qf[q2][ks][1] = tf32c(q1[ks * 8 + t] * scale);
            qf[q2][ks][2] = tf32c(q0[ks * 8 + 4 + t] * scale);
            qf[q2][ks][3] = tf32c(q1[ks * 8 + 4 + t] * scale);
        }
    }

    float4 o0[4], o1[4];
#pragma unroll
    for (int i = 0; i < 4; i++) {
        o0[i] = make_float4(0.f, 0.f, 0.f, 0.f);
        o1[i] = make_float4(0.f, 0.f, 0.f, 0.f);
    }
    float l00 = 0.f, l01 = 0.f, l10 = 0.f, l11 = 0.f;

    const int lr = tid >> 3;
    const int lc = (tid & 7) * 4;
    const unsigned fullm = 0xffffffffu;
    const int src0 = (lane & 28) | (t >> 1);
    const int src2 = src0 + 2;
    const bool odd = (t & 1);

    for (int ch = 0; ch < 16; ch++) {
        const int kbase = ch * 64;
#pragma unroll
        for (int p = 0; p < 2; p++) {
            int r = lr + p * 32;
            const float* src = qkv + (size_t)(b * MM + kbase + r) * 768 + h * 32 + lc;
            float4 vk = *(const float4*)(src + 256);
            float4 vv = *(const float4*)(src + 512);
            *(uint4*)&Ks[r * 36 + lc] = make_uint4(tf32c(vk.x), tf32c(vk.y), tf32c(vk.z), tf32c(vk.w));
            *(uint4*)&Vs[r * 40 + lc] = make_uint4(tf32c(vv.x), tf32c(vv.y), tf32c(vv.z), tf32c(vv.w));
        }
        __syncthreads();

#pragma unroll
        for (int ns = 0; ns < 8; ns++) {
            float4 s0 = make_float4(0.f, 0.f, 0.f, 0.f);
            float4 s1 = make_float4(0.f, 0.f, 0.f, 0.f);
#pragma unroll
            for (int ks = 0; ks < 4; ks++) {
                int nrow = ns * 8 + g;
                unsigned b0 = Ks[nrow * 36 + ks * 8 + t];
                unsigned b1 = Ks[nrow * 36 + ks * 8 + 4 + t];
                mma_tf32(s0, qf[0][ks][0], qf[0][ks][1], qf[0][ks][2], qf[0][ks][3], b0, b1);
                mma_tf32(s1, qf[1][ks][0], qf[1][ks][1], qf[1][ks][2], qf[1][ks][3], b0, b1);
            }
            s0.x = __expf(s0.x); s0.y = __expf(s0.y); s0.z = __expf(s0.z); s0.w = __expf(s0.w);
            s1.x = __expf(s1.x); s1.y = __expf(s1.y); s1.z = __expf(s1.z); s1.w = __expf(s1.w);
            l00 += s0.x + s0.y; l01 += s0.z + s0.w;
            l10 += s1.x + s1.y; l11 += s1.z + s1.w;

            float ax0 = __shfl_sync(fullm, s0.x, src0);
            float ay0 = __shfl_sync(fullm, s0.y, src0);
            float az0 = __shfl_sync(fullm, s0.z, src0);
            float aw0 = __shfl_sync(fullm, s0.w, src0);
            float ax2 = __shfl_sync(fullm, s0.x, src2);
            float ay2 = __shfl_sync(fullm, s0.y, src2);
            float az2 = __shfl_sync(fullm, s0.z, src2);
            float aw2 = __shfl_sync(fullm, s0.w, src2);
            unsigned pa0 = tf32c(odd ? ay0 : ax0);
            unsigned pa1 = tf32c(odd ? aw0 : az0);
            unsigned pa2 = tf32c(odd ? ay2 : ax2);
            unsigned pa3 = tf32c(odd ? aw2 : az2);

            float bx0 = __shfl_sync(fullm, s1.x, src0);
            float by0 = __shfl_sync(fullm, s1.y, src0);
            float bz0 = __shfl_sync(fullm, s1.z, src0);
            float bw0 = __shfl_sync(fullm, s1.w, src0);
            float bx2 = __shfl_sync(fullm, s1.x, src2);
            float by2 = __shfl_sync(fullm, s1.y, src2);
            float bz2 = __shfl_sync(fullm, s1.z, src2);
            float bw2 = __shfl_sync(fullm, s1.w, src2);
            unsigned pb0 = tf32c(odd ? by0 : bx0);
            unsigned pb1 = tf32c(odd ? bw0 : bz0);
            unsigned pb2 = tf32c(odd ? by2 : bx2);
            unsigned pb3 = tf32c(odd ? bw2 : bz2);

#pragma unroll
            for (int ds = 0; ds < 4; ds++) {
                unsigned v0 = Vs[(ns * 8 + t) * 40 + ds * 8 + g];
                unsigned v1 = Vs[(ns * 8 + 4 + t) * 40 + ds * 8 + g];
                mma_tf32(o0[ds], pa0, pa1, pa2, pa3, v0, v1);
                mma_tf32(o1[ds], pb0, pb1, pb2, pb3, v0, v1);
            }
        }
        __syncthreads();
    }

    l00 += __shfl_xor_sync(fullm, l00, 1); l00 += __shfl_xor_sync(fullm, l00, 2);
    l01 += __shfl_xor_sync(fullm, l01, 1); l01 += __shfl_xor_sync(fullm, l01, 2);
    l10 += __shfl_xor_sync(fullm, l10, 1); l10 += __shfl_xor_sync(fullm, l10, 2);
    l11 += __shfl_xor_sync(fullm, l11, 1); l11 += __shfl_xor_sync(fullm, l11, 2);
    float i00 = 1.f / l00, i01 = 1.f / l01;
    float i10 = 1.f / l10, i11 = 1.f / l11;

    float* p0 = out + (size_t)(b * MM + qw + g) * DD + h * 32;
    float* p1 = out + (size_t)(b * MM + qw + g + 8) * DD + h * 32;
#pragma unroll
    for (int ds = 0; ds < 4; ds++) {
        int col = ds * 8 + t * 2;
        *(float2*)(p0 + col) = make_float2(o0[ds].x * i00, o0[ds].y * i00);
        *(float2*)(p1 + col) = make_float2(o0[ds].z * i01, o0[ds].w * i01);
    }
    float* p2 = out + (size_t)(b * MM + qw + 16 + g) * DD + h * 32;
    float* p3 = out + (size_t)(b * MM + qw + 16 + g + 8) * DD + h * 32;
#pragma unroll
    for (int ds = 0; ds < 4; ds++) {
        int col = ds * 8 + t * 2;
        *(float2*)(p2 + col) = make_float2(o1[ds].x * i10, o1[ds].y * i10);
        *(float2*)(p3 + col) = make_float2(o1[ds].z * i11, o1[ds].w * i11);
    }
}

// ---------------- stage2 fat kernel: attention + csc/csr builds + inc copy + g_sum zero ----
// block ranges: [0,256) attn | [256,304) csc | [304,1328) csr | [1328,2352) copy | 2352 zero
#define S2_ATTN 256
#define S2_CSC  (S2_ATTN + 48)
#define S2_CSR  (S2_CSC + 1024)
#define S2_COPY (S2_CSR + 1024)
#define S2_TOT  (S2_COPY + 1)

__global__ void __launch_bounds__(256, 2)
stage2(const float* __restrict__ qkv, float* __restrict__ attn_out,
       const float* __restrict__ inc, float* __restrict__ out_inc, int do_copy)
{
    __shared__ unsigned sh[64 * 36 + 64 * 40];
    const int bid = blockIdx.x;
    const int tid = threadIdx.x;

    if (bid < S2_ATTN) {
        attn_body(qkv, attn_out, bid >> 2, bid & 3, sh, sh + 64 * 36);
    } else if (bid < S2_CSC) {
        // CSC: one thread per (b,e)
        int ge = (bid - S2_ATTN) * 256 + tid;
        int b = ge / EE, e = ge % EE;
        const float* p = inc + (size_t)b * MM * EE + e;
        unsigned short* lst = g_csc_idx + (size_t)ge * CAP;
        int cnt = 0;
        for (int m = 0; m < MM; m++) {
            if (p[(size_t)m * EE] != 0.f) {
                if (cnt < CAP) lst[cnt] = (unsigned short)m;
                cnt++;
            }
        }
        g_csc_cnt[ge] = cnt < CAP ? cnt : CAP;
    } else if (bid < S2_CSR) {
        // CSR: one warp per (b,m)
        int wid = ((bid - S2_CSC) * 256 + tid) >> 5;
        int lane = tid & 31;
        const float* p = inc + (size_t)wid * EE;
        unsigned short* lst = g_csr_idx + (size_t)wid * CAP;
        int cnt = 0;
        for (int eb = 0; eb < EE; eb += 32) {
            float v = p[eb + lane];
            unsigned mask = __ballot_sync(0xffffffffu, v != 0.f);
            if (v != 0.f) {
                int pos = cnt + __popc(mask & ((1u << lane) - 1u));
                if (pos < CAP) lst[pos] = (unsigned short)(eb + lane);
            }
            cnt += __popc(mask);
        }
        if (lane == 0) g_csr_cnt[wid] = cnt < CAP ? cnt : CAP;
    } else if (bid < S2_COPY) {
        if (do_copy) {
            const int n4 = BB * MM * EE / 4;
            const int stride = 1024 * 256;
            for (int i = (bid - S2_CSR) * 256 + tid; i < n4; i += stride)
                ((float4*)out_inc)[i] = ((const float4*)inc)[i];
        }
    } else {
        // zero g_sum for atomic accumulation
        for (int i = tid; i < BB * DD; i += 256) g_sum[i] = 0.f;
    }
}

// ---------------- sparse aggregation (unroll 8). SCALE: multiply by 1/(3+*sc) ----------------
template<bool SCALE>
__global__ void __launch_bounds__(256)
spmm_gather(const unsigned short* __restrict__ idx, const int* __restrict__ cnt,
            const float* __restrict__ X, float* __restrict__ O,
            int groups_per_b, int rows_per_b, const float* __restrict__ sc)
{
    int g = blockIdx.x * 4 + (threadIdx.x >> 6);
    int b = g / groups_per_b;
    int t = threadIdx.x & 63;
    int c = cnt[g];
    const unsigned short* lst = idx + (size_t)g * CAP;
    const float* Xb = X + (size_t)b * rows_per_b * DD + t * 4;
    float4 s = make_float4(0.f, 0.f, 0.f, 0.f);
    float4 s2 = make_float4(0.f, 0.f, 0.f, 0.f);
    int i = 0;
    for (; i + 8 <= c; i += 8) {
        int r0 = lst[i], r1 = lst[i+1], r2 = lst[i+2], r3 = lst[i+3];
        int r4 = lst[i+4], r5 = lst[i+5], r6 = lst[i+6], r7 = lst[i+7];
        float4 v0 = *(const float4*)(Xb + (size_t)r0 * DD);
        float4 v1 = *(const float4*)(Xb + (size_t)r1 * DD);
        float4 v2 = *(const float4*)(Xb + (size_t)r2 * DD);
        float4 v3 = *(const float4*)(Xb + (size_t)r3 * DD);
        float4 v4 = *(const float4*)(Xb + (size_t)r4 * DD);
        float4 v5 = *(const float4*)(Xb + (size_t)r5 * DD);
        float4 v6 = *(const float4*)(Xb + (size_t)r6 * DD);
        float4 v7 = *(const float4*)(Xb + (size_t)r7 * DD);
        s.x += v0.x; s.y += v0.y; s.z += v0.z; s.w += v0.w;
        s2.x += v1.x; s2.y += v1.y; s2.z += v1.z; s2.w += v1.w;
        s.x += v2.x; s.y += v2.y; s.z += v2.z; s.w += v2.w;
        s2.x += v3.x; s2.y += v3.y; s2.z += v3.z; s2.w += v3.w;
        s.x += v4.x; s.y += v4.y; s.z += v4.z; s.w += v4.w;
        s2.x += v5.x; s2.y += v5.y; s2.z += v5.z; s2.w += v5.w;
        s.x += v6.x; s.y += v6.y; s.z += v6.z; s.w += v6.w;
        s2.x += v7.x; s2.y += v7.y; s2.z += v7.z; s2.w += v7.w;
    }
    for (; i < c; i++) {
        int r = lst[i];
        float4 v = *(const float4*)(Xb + (size_t)r * DD);
        s.x += v.x; s.y += v.y; s.z += v.z; s.w += v.w;
    }
    s.x += s2.x; s.y += s2.y; s.z += s2.z; s.w += s2.w;
    if (SCALE) {
        float f = 1.f / (3.f + *sc);
        s.x *= f; s.y *= f; s.z *= f; s.w *= f;
    }
    *(float4*)(O + (size_t)g * DD + t * 4) = s;
}

// ---------------- softmax stats: g_sum[b,d] += partial sum_e exp(S[b,e,d]) ----------------
// grid (DD/32, BB, 4): z splits the e-range into 4 chunks of 384
__global__ void softmax_stats(const float* __restrict__ S, float* __restrict__ sump)
{
    const int b = blockIdx.y;
    const int tx = threadIdx.x, ty = threadIdx.y;
    const int d = blockIdx.x * 32 + tx;
    const int e0 = blockIdx.z * (EE / 4);
    __shared__ float sm[32][33];

    const float* Sb = S + (size_t)b * EE * DD + d;
    float sum = 0.f;
    for (int e = e0 + ty; e < e0 + EE / 4; e += 32) sum += __expf(Sb[(size_t)e * DD]);
    sm[ty][tx] = sum; __syncthreads();
    for (int s = 16; s > 0; s >>= 1) {
        if (ty < s) sm[ty][tx] += sm[ty + s][tx];
        __syncthreads();
    }
    if (ty == 0) atomicAdd(&sump[b * DD + d], sm[0][tx]);
}

// ---------------- reductions ----------------
__device__ __forceinline__ float warp_sum(float v) {
#pragma unroll
    for (int o = 16; o > 0; o >>= 1) v += __shfl_down_sync(0xffffffffu, v, o);
    return v;
}

__device__ __forceinline__ float block_sum256(float v, float* red, float* bc) {
    int lane = threadIdx.x & 31, w = threadIdx.x >> 5;
    float t = warp_sum(v);
    if (lane == 0) red[w] = t;
    __syncthreads();
    if (w == 0) {
        float u = (lane < 8) ? red[lane] : 0.f;
#pragma unroll
        for (int o = 4; o > 0; o >>= 1) u += __shfl_down_sync(0xffffffffu, u, o);
        if (lane == 0) *bc = u;
    }
    __syncthreads();
    return *bc;
}

// LN -> out_edge = (3+av) * LN(X)
__global__ void ln_edge_kernel(const float* __restrict__ X, const float* __restrict__ g,
                               const float* __restrict__ bb, const float* __restrict__ p_av,
                               float* __restrict__ out_edge)
{
    const int row = blockIdx.x;
    const int d = threadIdx.x;
    __shared__ float red[8];
    __shared__ float bc;

    float x = X[(size_t)row * DD + d];
    float mu = block_sum256(x, red, &bc) * (1.f / DD);
    float dv = x - mu;
    __syncthreads();
    float var = block_sum256(dv * dv, red, &bc) * (1.f / DD);

    float v = dv * rsqrtf(var + LN_EPS) * g[d] + bb[d];
    out_edge[(size_t)row * DD + d] = (3.f + *p_av) * v;
}

__global__ void final_node_kernel(const float* __restrict__ Y, const float* __restrict__ feat,
                                  const float* __restrict__ g, const float* __restrict__ bb,
                                  const float* __restrict__ p_av, const float* __restrict__ p_ae,
                                  float* __restrict__ out)
{
    const int row = blockIdx.x;
    const int d = threadIdx.x;
    __shared__ float red[8];
    __shared__ float bc;

    float y = Y[(size_t)row * DD + d];
    float mu = block_sum256(y, red, &bc) * (1.f / DD);
    float z = y - mu;
    __syncthreads();
    float vr = block_sum256(z * z, red, &bc) * (1.f / DD);

    const float ae = *p_ae, av = *p_av;
    const float gd = g[d], bd = bb[d];
    const float c3 = 3.f + av;
    const float t1 = z * rsqrtf(vr + LN_EPS) * gd + bd;
    const float t2 = 2.f * z * rsqrtf(4.f * vr + LN_EPS) * gd + bd;
    const float t3 = c3 * z * rsqrtf(c3 * c3 * vr + LN_EPS) * gd + bd;

    const float op = 1.f + ae;
    out[(size_t)row * DD + d] =
        op * op * op * feat[(size_t)row * DD + d] +
        (1.f - ae) * (op * op * t1 + op * t2 + t3);
}

// ---------------- host ----------------
extern "C" void kernel_launch(void* const* d_in, const int* in_sizes, int n_in,
                              void* d_out, int out_size)
{
    const float* feat     = (const float*)d_in[0];
    const float* inc      = (const float*)d_in[1];
    const float* vc_Win   = (const float*)d_in[2];
    const float* vc_bin   = (const float*)d_in[3];
    const float* vc_Wout  = (const float*)d_in[4];
    const float* vc_bout  = (const float*)d_in[5];
    const float* vc_Wproj = (const float*)d_in[6];
    const float* vc_g     = (const float*)d_in[7];
    const float* vc_b     = (const float*)d_in[8];
    const float* vc_alpha = (const float*)d_in[9];
    const float* ec_Wproj = (const float*)d_in[14];
    const float* ec_g     = (const float*)d_in[15];
    const float* ec_b     = (const float*)d_in[16];
    const float* ec_alpha = (const float*)d_in[17];

    float *qkv, *attn, *A, *S, *Ep, *Y1, *Y, *sump;
    unsigned short *csc_idx, *csr_idx;
    int *csc_cnt, *csr_cnt;
    cudaGetSymbolAddress((void**)&qkv,  g_qkv);
    cudaGetSymbolAddress((void**)&attn, g_attn);
    cudaGetSymbolAddress((void**)&A,    g_A);
    cudaGetSymbolAddress((void**)&S,    g_S);
    cudaGetSymbolAddress((void**)&Ep,   g_Ep);
    cudaGetSymbolAddress((void**)&Y1,   g_Y1);
    cudaGetSymbolAddress((void**)&Y,    g_Y);
    cudaGetSymbolAddress((void**)&sump, g_sum);
    cudaGetSymbolAddress((void**)&csc_idx, g_csc_idx);
    cudaGetSymbolAddress((void**)&csr_idx, g_csr_idx);
    cudaGetSymbolAddress((void**)&csc_cnt, g_csc_cnt);
    cudaGetSymbolAddress((void**)&csr_cnt, g_csr_cnt);

    const int NODE = BB * MM * DD;
    const int EDGE = BB * EE * DD;
    const int INC  = BB * MM * EE;
    float* out_node = (float*)d_out;
    float* out_edge = out_node + NODE;
    float* out_inc  = out_edge + EDGE;
    const int do_copy = (out_size >= NODE + EDGE + INC) ? 1 : 0;

    // 1) QKV = feat @ vc_Win^T + vc_bin
    gemm_mma<true, false><<<dim3(6, 64), 256>>>(feat, vc_Win, vc_bin, qkv, 768, 256, nullptr);

    // 2) fat kernel: attention + csc/csr builds + inc copy + g_sum zero
    stage2<<<S2_TOT, 256>>>(qkv, attn, inc, out_inc, do_copy);

    // 3) A = attn @ vc_Wout^T + vc_bout
    gemm_mma<true, false><<<dim3(2, 64), 256>>>(attn, vc_Wout, vc_bout, A, 256, 256, nullptr);

    // 4) S[b,e,:] = sum_m inc[b,m,e] * A[b,m,:]
    spmm_gather<false><<<BB * EE / 4, 256>>>(csc_idx, csc_cnt, A, S, EE, MM, nullptr);

    // 5) g_sum[b,d] = sum_e exp(S)  (4-way e-split, atomic combine)
    softmax_stats<<<dim3(DD / 32, BB, 4), dim3(32, 32)>>>(S, sump);

    // 6) Ep = (S * exp(S) / colsum) @ vc_Wproj^T   (edge weighting fused in A-load)
    gemm_mma<false, true><<<dim3(2, 96), 256>>>(S, vc_Wproj, nullptr, Ep, 256, 256, sump);

    // 7) out_edge = (3+av) * LN(Ep)
    ln_edge_kernel<<<BB * EE, DD>>>(Ep, vc_g, vc_b, vc_alpha, out_edge);

    // 8) Y1[b,m,:] = sum_e inc[b,m,e] * E0[b,e,:]  (E0 = out_edge / (3+av))
    spmm_gather<true><<<BB * MM / 4, 256>>>(csr_idx, csr_cnt, out_edge, Y1, MM, EE, vc_alpha);

    // 9) Y = Y1 @ ec_Wproj^T
    gemm_mma<false, false><<<dim3(2, 64), 256>>>(Y1, ec_Wproj, nullptr, Y, 256, 256, nullptr);

    // 10) node output
    final_node_kernel<<<BB * MM, DD>>>(Y, feat, ec_g, ec_b, vc_alpha, ec_alpha, out_node);
}